// round 9
// baseline (speedup 1.0000x reference)
#include <cuda_runtime.h>
#include <cuda_fp16.h>
#include <mma.h>
#include <math.h>
#include <stdint.h>

using namespace nvcuda;

// Problem constants
#define B_    8
#define T_    2048
#define R_    (B_*T_)     // 16384 rows
#define VDIM_ 1024
#define ADIM_ 768
#define DM_   256
#define HID_  1024
#define XDIM_ 768         // 3*DM
#define NBLK_ 8           // HID / 128 column blocks for gate GEMM

// Scratch (__device__ globals; allocation-free rule)
__device__ __align__(16) float g_v[R_*DM_];      // raw video proj -> LN'd in place
__device__ float g_rv[R_];                       // 1/max(||v_row||,eps)
__device__ __align__(16) float g_a[R_*DM_];      // raw audio proj -> LN'd in place
__device__ __align__(16) float g_actx[R_*DM_];   // audio context (full precision)
__device__ __align__(16) __half g_Xh[R_*XDIM_];  // [an, vn, an*vn] in fp16
__device__ float g_plog[R_*NBLK_];               // partial logits
// fp16 weights
__device__ __align__(16) __half g_wv[VDIM_*DM_];
__device__ __align__(16) __half g_wa[ADIM_*DM_];
__device__ __align__(16) __half g_w1[XDIM_*HID_];

__device__ __forceinline__ uint32_t smem_u32(const void* p) {
    uint32_t a;
    asm("{ .reg .u64 t; cvta.to.shared.u64 t, %1; cvt.u32.u64 %0, t; }"
        : "=r"(a) : "l"(p));
    return a;
}
#define CP16(dst_u32, src_ptr) \
    asm volatile("cp.async.cg.shared.global [%0], [%1], 16;" \
                 :: "r"(dst_u32), "l"(src_ptr) : "memory")
#define CP_COMMIT() asm volatile("cp.async.commit_group;" ::: "memory")
#define CP_WAIT(n)  asm volatile("cp.async.wait_group %0;" :: "n"(n) : "memory")

__device__ __forceinline__ uint32_t pkh2(float a, float b) {
    __half2 h = __floats2half2_rn(a, b);
    return *reinterpret_cast<uint32_t*>(&h);
}

// ---------------------------------------------------------------------------
// prep: convert weights fp32 -> fp16.
// ---------------------------------------------------------------------------
__global__ __launch_bounds__(256) void prep_wh(
    const float* __restrict__ W, __half* __restrict__ Wo, int n4)
{
    int i = blockIdx.x * 256 + threadIdx.x;
    if (i < n4) {
        float4 v = ((const float4*)W)[i];
        uint2 o = make_uint2(pkh2(v.x, v.y), pkh2(v.z, v.w));
        *(uint2*)(Wo + (size_t)i * 4) = o;
    }
}

// ---------------------------------------------------------------------------
// FP16 wmma GEMM (fp32 accum): C[R x NOUT] = A[R x KD] @ Bt[KD x NOUT].
// CTA tile 128x128, BK=32 (2 kk-steps of k16), 256 thr, 8 warps (4x2),
// warp tile 32x64. 3-stage smem pipeline, ONE __syncthreads per chunk:
// chunk i+2's async writes target the stage last read by chunk i-1, which
// the iteration-i arrival barrier already fences. cp.async runs 2 deep.
// __launch_bounds__(256,2): 128-reg cap -> 2 CTAs/SM.
// Bt fp16 -> cp.async. A: AASYNC ? cp.async (fp16 src) : LDG fp32 -> cvt -> STS.
// EPI=0: raw fp32 C to Cout. EPI=1: mlp epilogue (bias + exact gelu . W2).
// ---------------------------------------------------------------------------
#define ALDH 40                      // A smem leading dim (halves)
#define BLDH 136                     // B smem leading dim (halves)
#define AHALF (128*ALDH)             // 5120 halves
#define STGH (AHALF + 32*BLDH)       // 9472 halves = 18944 B per stage

template<int NCH, int NOUT, bool AASYNC, bool EPI>
__global__ __launch_bounds__(256, 2) void gemm_h(
    const void* __restrict__ Ap, const __half* __restrict__ Bt,
    const float* __restrict__ b1v, const float* __restrict__ W2v,
    float* __restrict__ Cout)
{
    extern __shared__ __align__(16) char smraw[];
    __half* sh = (__half*)smraw;
    const int tid  = threadIdx.x;
    const int lane = tid & 31;
    const int warp = tid >> 5;
    const int wr   = warp >> 1;         // 0..3 (32-row block)
    const int wc   = warp & 1;          // 0..1 (64-col block)
    const int row0 = blockIdx.x * 128;
    const int n0   = blockIdx.y * 128;
    const int KD   = NCH * 32;

    wmma::fragment<wmma::accumulator, 16, 16, 16, float> acc[2][4];
#pragma unroll
    for (int i = 0; i < 2; i++)
#pragma unroll
        for (int j = 0; j < 4; j++) wmma::fill_fragment(acc[i][j], 0.f);

    // sync-A path mapping (proj): 16 floats/thread
    const int ar = tid >> 3;            // rows 0..31 (+32*j)
    const int ac = (tid & 7) << 2;      // cols 0,4,..,28

    float4 areg[4];

    auto ldgA = [&](int i) {
        const float* Af = (const float*)Ap;
        const float* Ab = Af + (size_t)row0 * KD + i * 32;
#pragma unroll
        for (int j = 0; j < 4; j++)
            areg[j] = *(const float4*)(Ab + (size_t)(ar + 32 * j) * KD + ac);
    };
    auto stsA = [&](__half* As) {
#pragma unroll
        for (int j = 0; j < 4; j++) {
            uint2 o = make_uint2(pkh2(areg[j].x, areg[j].y),
                                 pkh2(areg[j].z, areg[j].w));
            *(uint2*)(As + (ar + 32 * j) * ALDH + ac) = o;
        }
    };
    auto cpA = [&](int i, __half* As) {
        const __half* Ah = (const __half*)Ap;
#pragma unroll
        for (int j = 0; j < 2; j++) {
            int idx = tid + j * 256;
            int r   = idx >> 2;
            int sg  = (idx & 3) << 3;
            CP16(smem_u32(As + r * ALDH + sg),
                 Ah + (size_t)(row0 + r) * KD + i * 32 + sg);
        }
    };
    auto cpB = [&](int i, __half* Bs) {
#pragma unroll
        for (int j = 0; j < 2; j++) {
            int idx = tid + j * 256;
            int r   = idx >> 4;
            int sg  = (idx & 15) << 3;
            CP16(smem_u32(Bs + r * BLDH + sg),
                 Bt + (size_t)(i * 32 + r) * NOUT + n0 + sg);
        }
    };

    // Prologue: chunks 0 and 1 (one commit group each)
    if (AASYNC) {
        cpA(0, sh);          cpB(0, sh + AHALF);          CP_COMMIT();
        cpA(1, sh + STGH);   cpB(1, sh + STGH + AHALF);   CP_COMMIT();
    } else {
        ldgA(0); stsA(sh);   cpB(0, sh + AHALF);          CP_COMMIT();
        ldgA(1);             cpB(1, sh + STGH + AHALF);   CP_COMMIT();
        // regs now hold chunk 1's A
    }

#pragma unroll
    for (int i = 0; i < NCH; i++) {
        const int s = i % 3;
        if (i < NCH - 1) CP_WAIT(1); else CP_WAIT(0);
        __syncthreads();   // chunk i ready; stages (i+1)%3,(i+2)%3 free for writes

        if (!AASYNC) {
            if (i + 1 < NCH) stsA(sh + ((i + 1) % 3) * STGH);  // regs = chunk i+1
        }
        if (i + 2 < NCH) {
            __half* Sn = sh + ((i + 2) % 3) * STGH;
            if (AASYNC) cpA(i + 2, Sn);
            cpB(i + 2, Sn + AHALF);
            CP_COMMIT();
            if (!AASYNC) ldgA(i + 2);   // hide LDG under chunk i compute
        }

        __half* As = sh + s * STGH;
        __half* Bs = As + AHALF;
#pragma unroll
        for (int kk = 0; kk < 32; kk += 16) {
            wmma::fragment<wmma::matrix_a, 16, 16, 16, __half,
                           wmma::row_major> af[2];
            wmma::fragment<wmma::matrix_b, 16, 16, 16, __half,
                           wmma::row_major> bf[4];
#pragma unroll
            for (int u = 0; u < 2; u++)
                wmma::load_matrix_sync(af[u],
                    As + (wr * 32 + u * 16) * ALDH + kk, ALDH);
#pragma unroll
            for (int v = 0; v < 4; v++)
                wmma::load_matrix_sync(bf[v],
                    Bs + kk * BLDH + wc * 64 + v * 16, BLDH);
#pragma unroll
            for (int u = 0; u < 2; u++)
#pragma unroll
                for (int v = 0; v < 4; v++)
                    wmma::mma_sync(acc[u][v], af[u], bf[v], acc[u][v]);
        }
    }

    if (!EPI) {
#pragma unroll
        for (int u = 0; u < 2; u++)
#pragma unroll
            for (int v = 0; v < 4; v++)
                wmma::store_matrix_sync(
                    Cout + (size_t)(row0 + wr * 32 + u * 16) * NOUT
                         + n0 + wc * 64 + v * 16,
                    acc[u][v], NOUT, wmma::mem_row_major);
    } else {
        __syncthreads();   // all warps done reading stages before smem reuse
        float* Cs = (float*)smraw;   // 128 x 132 fp32
#pragma unroll
        for (int u = 0; u < 2; u++)
#pragma unroll
            for (int v = 0; v < 4; v++)
                wmma::store_matrix_sync(
                    Cs + (wr * 32 + u * 16) * 132 + wc * 64 + v * 16,
                    acc[u][v], 132, wmma::mem_row_major);
        __syncthreads();

        float b1f[4], w2f[4];
#pragma unroll
        for (int q = 0; q < 4; q++) {
            int gcol = n0 + lane + q * 32;
            b1f[q] = b1v[gcol];
            w2f[q] = W2v[gcol];
        }
#pragma unroll
        for (int rr = 0; rr < 16; rr++) {
            int r = warp * 16 + rr;
            float p = 0.f;
#pragma unroll
            for (int q = 0; q < 4; q++) {
                float x = Cs[r * 132 + lane + q * 32] + b1f[q];
                float h = 0.5f * x * (1.f + erff(x * 0.7071067811865476f));
                p = fmaf(h, w2f[q], p);
            }
#pragma unroll
            for (int off = 16; off > 0; off >>= 1)
                p += __shfl_xor_sync(0xffffffffu, p, off);
            if (lane == 0)
                g_plog[(size_t)(row0 + r) * NBLK_ + blockIdx.y] = p;
        }
    }
}

// ---------------------------------------------------------------------------
// LN pass: adds bias, LayerNorms in place. y=0 -> g_v (+g_rv), y=1 -> g_a.
// ---------------------------------------------------------------------------
__global__ __launch_bounds__(256) void ln_kernel(
    const float* __restrict__ bv, const float* __restrict__ ba)
{
    __shared__ float redS[8], redQ[8], bc2[2];
    const int row = blockIdx.x;
    const int d   = threadIdx.x;
    float* buf = blockIdx.y ? g_a : g_v;
    const float* bias = blockIdx.y ? ba : bv;

    float x = buf[(size_t)row * DM_ + d] + bias[d];
    float s = x, q = x * x;
#pragma unroll
    for (int off = 16; off > 0; off >>= 1) {
        s += __shfl_xor_sync(0xffffffffu, s, off);
        q += __shfl_xor_sync(0xffffffffu, q, off);
    }
    int lane = d & 31, warp = d >> 5;
    if (lane == 0) { redS[warp] = s; redQ[warp] = q; }
    __syncthreads();
    if (d == 0) {
        float ts = 0.f, tq = 0.f;
#pragma unroll
        for (int k = 0; k < 8; k++) { ts += redS[k]; tq += redQ[k]; }
        float mu  = ts * (1.f / 256.f);
        float var = fmaxf(tq * (1.f / 256.f) - mu * mu, 0.f);
        bc2[0] = mu;
        bc2[1] = rsqrtf(var + 1e-5f);
        if (blockIdx.y == 0) {
            float l2 = sqrtf(256.f * var) * bc2[1];
            g_rv[row] = 1.f / fmaxf(l2, 1e-8f);
        }
    }
    __syncthreads();
    buf[(size_t)row * DM_ + d] = (x - bc2[0]) * bc2[1];
}

// ---------------------------------------------------------------------------
// ctx: temporal shift + causal 6-tap window avg + l2 norms + build X (fp16).
// 4 rows/block, 64 threads/row, float4 per thread. center==t (delta in (2,6)).
// ---------------------------------------------------------------------------
__global__ __launch_bounds__(256) void ctx_kernel(const float* __restrict__ theta)
{
    __shared__ float red2[4][2];
    const int tid = threadIdx.x;
    const int rl  = tid >> 6;
    const int q   = tid & 63;
    const int row = blockIdx.x * 4 + rl;
    const int b   = row >> 11;
    const int t   = row & 2047;

    float th    = fminf(fmaxf(theta[0], -12.f), 12.f);
    float delta = 2.f + 4.f / (1.f + expf(-th));
    float nf    = floorf(delta);
    float alpha = delta - nf;
    int   ni    = (int)nf;

    const int lo = max(0, t - 5);
    const float inv_cnt = 1.f / (float)(t - lo + 1);

    const float* ab = g_a + (size_t)b * T_ * DM_;
    float4 acc = {0.f, 0.f, 0.f, 0.f};
    for (int tau = lo; tau <= t; tau++) {
        int i0 = min(max(tau - ni, 0), T_ - 1);
        int i1 = min(i0 + 1, T_ - 1);
        float4 x0 = *(const float4*)(ab + (size_t)i0 * DM_ + q * 4);
        float4 x1 = *(const float4*)(ab + (size_t)i1 * DM_ + q * 4);
        acc.x += (1.f - alpha) * x0.x + alpha * x1.x;
        acc.y += (1.f - alpha) * x0.y + alpha * x1.y;
        acc.z += (1.f - alpha) * x0.z + alpha * x1.z;
        acc.w += (1.f - alpha) * x0.w + alpha * x1.w;
    }
    float4 ac = {acc.x * inv_cnt, acc.y * inv_cnt, acc.z * inv_cnt, acc.w * inv_cnt};

    float ss = ac.x * ac.x + ac.y * ac.y + ac.z * ac.z + ac.w * ac.w;
#pragma unroll
    for (int off = 16; off > 0; off >>= 1)
        ss += __shfl_xor_sync(0xffffffffu, ss, off);
    const int wp = tid >> 5;
    if ((tid & 31) == 0) red2[wp >> 1][wp & 1] = ss;
    __syncthreads();
    float tot = red2[rl][0] + red2[rl][1];
    float ra  = 1.f / fmaxf(sqrtf(tot), 1e-8f);

    float4 vv = *(const float4*)(g_v + (size_t)row * DM_ + q * 4);
    float rv  = g_rv[row];

    *(float4*)(g_actx + (size_t)row * DM_ + q * 4) = ac;

    float vnx = vv.x * rv, vny = vv.y * rv, vnz = vv.z * rv, vnw = vv.w * rv;
    float anx = ac.x * ra, any_ = ac.y * ra, anz = ac.z * ra, anw = ac.w * ra;

    __half* xr = g_Xh + (size_t)row * XDIM_;
    *(uint2*)(xr + q * 4) =
        make_uint2(pkh2(anx, any_), pkh2(anz, anw));
    *(uint2*)(xr + DM_ + q * 4) =
        make_uint2(pkh2(vnx, vny), pkh2(vnz, vnw));
    *(uint2*)(xr + 2 * DM_ + q * 4) =
        make_uint2(pkh2(anx * vnx, any_ * vny), pkh2(anz * vnz, anw * vnw));
}

// ---------------------------------------------------------------------------
// out: finish logit, gate, mix. float4 per thread.
// ---------------------------------------------------------------------------
__global__ __launch_bounds__(256) void out_kernel(
    const float* __restrict__ b2, float* __restrict__ out)
{
    const int idx = blockIdx.x * 256 + threadIdx.x;   // over R_*64 float4s
    const int row = idx >> 6;
    const int c4  = (idx & 63) << 2;
    float s = b2[0];
#pragma unroll
    for (int k = 0; k < NBLK_; k++) s += g_plog[(size_t)row * NBLK_ + k];
    s = fminf(fmaxf(s, -12.f), 12.f);
    float g = 1.f / (1.f + expf(-s));
    g = fminf(fmaxf(g, 0.05f), 0.95f);
    float4 ac = *(const float4*)(g_actx + (size_t)row * DM_ + c4);
    float4 vv = *(const float4*)(g_v + (size_t)row * DM_ + c4);
    float4 o  = {g * ac.x + (1.f - g) * vv.x, g * ac.y + (1.f - g) * vv.y,
                 g * ac.z + (1.f - g) * vv.z, g * ac.w + (1.f - g) * vv.w};
    *(float4*)(out + (size_t)row * DM_ + c4) = o;
}

// ---------------------------------------------------------------------------
extern "C" void kernel_launch(void* const* d_in, const int* in_sizes, int n_in,
                              void* d_out, int out_size)
{
    const float* video = (const float*)d_in[0];
    const float* audio = (const float*)d_in[1];
    const float* Wv    = (const float*)d_in[2];
    const float* bv    = (const float*)d_in[3];
    const float* Wa    = (const float*)d_in[4];
    const float* ba    = (const float*)d_in[5];
    const float* theta = (const float*)d_in[6];
    const float* W1    = (const float*)d_in[7];
    const float* b1    = (const float*)d_in[8];
    const float* W2    = (const float*)d_in[9];
    const float* b2    = (const float*)d_in[10];
    float* out = (float*)d_out;

    float *gv, *ga;
    __half *gxh, *wv, *wa, *w1;
    cudaGetSymbolAddress((void**)&gv,  g_v);
    cudaGetSymbolAddress((void**)&ga,  g_a);
    cudaGetSymbolAddress((void**)&gxh, g_Xh);
    cudaGetSymbolAddress((void**)&wv,  g_wv);
    cudaGetSymbolAddress((void**)&wa,  g_wa);
    cudaGetSymbolAddress((void**)&w1,  g_w1);

    const int gsm = 3 * STGH * sizeof(__half);                 // 56832 B
    const int msm = (128 * 132 * 4 > gsm) ? 128 * 132 * 4 : gsm; // 67584 B
    cudaFuncSetAttribute(gemm_h<VDIM_/32, DM_, false, false>,
        cudaFuncAttributeMaxDynamicSharedMemorySize, gsm);
    cudaFuncSetAttribute(gemm_h<ADIM_/32, DM_, false, false>,
        cudaFuncAttributeMaxDynamicSharedMemorySize, gsm);
    cudaFuncSetAttribute(gemm_h<XDIM_/32, HID_, true, true>,
        cudaFuncAttributeMaxDynamicSharedMemorySize, msm);

    // weight prep (fp32 -> fp16)
    prep_wh<<<(VDIM_*DM_/4 + 255)/256, 256>>>(Wv, wv, VDIM_*DM_/4);
    prep_wh<<<(ADIM_*DM_/4 + 255)/256, 256>>>(Wa, wa, ADIM_*DM_/4);
    prep_wh<<<(XDIM_*HID_/4 + 255)/256, 256>>>(W1, w1, XDIM_*HID_/4);

    gemm_h<VDIM_/32, DM_, false, false><<<dim3(R_/128, 2), 256, gsm>>>(
        video, wv, nullptr, nullptr, gv);
    gemm_h<ADIM_/32, DM_, false, false><<<dim3(R_/128, 2), 256, gsm>>>(
        audio, wa, nullptr, nullptr, ga);
    ln_kernel<<<dim3(R_, 2), 256>>>(bv, ba);
    ctx_kernel<<<R_/4, 256>>>(theta);
    gemm_h<XDIM_/32, HID_, true, true><<<dim3(R_/128, NBLK_), 256, msm>>>(
        gxh, w1, b1, W2, nullptr);
    out_kernel<<<(R_*64)/256, 256>>>(b2, out);
}

// round 11
// speedup vs baseline: 1.0526x; 1.0526x over previous
#include <cuda_runtime.h>
#include <cuda_fp16.h>
#include <math.h>
#include <stdint.h>

// Problem constants
#define B_    8
#define T_    2048
#define R_    (B_*T_)     // 16384 rows
#define VDIM_ 1024
#define ADIM_ 768
#define DM_   256
#define HID_  1024
#define XDIM_ 768         // 3*DM
#define NBLK_ 8           // HID / 128 column blocks for gate GEMM

// Scratch (__device__ globals; allocation-free rule)
__device__ __align__(16) float g_v[R_*DM_];      // raw video proj -> LN'd in place
__device__ float g_rv[R_];                       // 1/max(||v_row||,eps)
__device__ __align__(16) float g_a[R_*DM_];      // raw audio proj -> LN'd in place
__device__ __align__(16) float g_actx[R_*DM_];   // audio context (full precision)
__device__ __align__(16) __half g_Xh[R_*XDIM_];  // [an, vn, an*vn] in fp16
__device__ float g_plog[R_*NBLK_];               // partial logits
// fp16 weights
__device__ __align__(16) __half g_wv[VDIM_*DM_];
__device__ __align__(16) __half g_wa[ADIM_*DM_];
__device__ __align__(16) __half g_w1[XDIM_*HID_];

__device__ __forceinline__ uint32_t smem_u32(const void* p) {
    uint32_t a;
    asm("{ .reg .u64 t; cvta.to.shared.u64 t, %1; cvt.u32.u64 %0, t; }"
        : "=r"(a) : "l"(p));
    return a;
}
#define CP16(dst_u32, src_ptr) \
    asm volatile("cp.async.cg.shared.global [%0], [%1], 16;" \
                 :: "r"(dst_u32), "l"(src_ptr) : "memory")
#define CP_COMMIT() asm volatile("cp.async.commit_group;" ::: "memory")
#define CP_WAIT(n)  asm volatile("cp.async.wait_group %0;" :: "n"(n) : "memory")

__device__ __forceinline__ uint32_t pkh2(float a, float b) {
    __half2 h = __floats2half2_rn(a, b);
    return *reinterpret_cast<uint32_t*>(&h);
}
__device__ __forceinline__ void ldmx4(uint32_t* r, uint32_t addr) {
    asm volatile("ldmatrix.sync.aligned.m8n8.x4.shared.b16 {%0,%1,%2,%3}, [%4];"
        : "=r"(r[0]), "=r"(r[1]), "=r"(r[2]), "=r"(r[3]) : "r"(addr));
}
__device__ __forceinline__ void ldmx4t(uint32_t* r, uint32_t addr) {
    asm volatile("ldmatrix.sync.aligned.m8n8.x4.trans.shared.b16 {%0,%1,%2,%3}, [%4];"
        : "=r"(r[0]), "=r"(r[1]), "=r"(r[2]), "=r"(r[3]) : "r"(addr));
}
__device__ __forceinline__ void mma16816(float* d, const uint32_t* a,
                                         const uint32_t* b) {
    asm volatile(
        "mma.sync.aligned.m16n8k16.row.col.f32.f16.f16.f32 "
        "{%0,%1,%2,%3}, {%4,%5,%6,%7}, {%8,%9}, {%0,%1,%2,%3};"
        : "+f"(d[0]), "+f"(d[1]), "+f"(d[2]), "+f"(d[3])
        : "r"(a[0]), "r"(a[1]), "r"(a[2]), "r"(a[3]), "r"(b[0]), "r"(b[1]));
}

// ---------------------------------------------------------------------------
// prep: convert weights fp32 -> fp16.
// ---------------------------------------------------------------------------
__global__ __launch_bounds__(256) void prep_wh(
    const float* __restrict__ W, __half* __restrict__ Wo, int n4)
{
    int i = blockIdx.x * 256 + threadIdx.x;
    if (i < n4) {
        float4 v = ((const float4*)W)[i];
        uint2 o = make_uint2(pkh2(v.x, v.y), pkh2(v.z, v.w));
        *(uint2*)(Wo + (size_t)i * 4) = o;
    }
}

// ---------------------------------------------------------------------------
// FP16 raw-mma GEMM (fp32 accum): C[R x KD] @ Bt[KD x NOUT], CTA tile 128x128,
// BK=32, 8 warps (4x2), warp tile 32x64. Explicit ldmatrix.x4(+trans) and
// mma.sync.m16n8k16 -- guarantees LDSM path (wmma may lower to scalar LDS).
// Per warp per chunk: 12 LDSM.x4 + 32 HMMA. 2-stage cp.async pipeline (R8).
// __launch_bounds__(256,2): 128-reg cap -> 2 CTAs/SM.
// EPI=0: raw fp32 C to Cout. EPI=1: mlp epilogue (bias + exact gelu . W2).
// ---------------------------------------------------------------------------
#define ALDH 40                      // A smem leading dim (halves): 20-word rows
#define BLDH 136                     // B smem leading dim (halves): 68-word rows
#define AHALF (128*ALDH)             // 5120 halves
#define STGH (AHALF + 32*BLDH)       // 9472 halves = 18944 B per stage

template<int NCH, int NOUT, bool AASYNC, bool EPI>
__global__ __launch_bounds__(256, 2) void gemm_m(
    const void* __restrict__ Ap, const __half* __restrict__ Bt,
    const float* __restrict__ b1v, const float* __restrict__ W2v,
    float* __restrict__ Cout)
{
    extern __shared__ __align__(16) char smraw[];
    __half* sh = (__half*)smraw;
    const int tid  = threadIdx.x;
    const int lane = tid & 31;
    const int warp = tid >> 5;
    const int wr   = warp >> 1;         // 0..3 (32-row block)
    const int wc   = warp & 1;          // 0..1 (64-col block)
    const int row0 = blockIdx.x * 128;
    const int n0   = blockIdx.y * 128;
    const int KD   = NCH * 32;

    // acc[u][w][4]: u = 16-row tile (2), w = 8-col tile (8)
    float acc[2][8][4];
#pragma unroll
    for (int u = 0; u < 2; u++)
#pragma unroll
        for (int w = 0; w < 8; w++)
#pragma unroll
            for (int x = 0; x < 4; x++) acc[u][w][x] = 0.f;

    // ldmatrix lane offsets (bytes)
    const int lrow = lane & 15;
    const int lhal = lane >> 4;
    const uint32_t loA = (uint32_t)(((wr * 32 + lrow) * ALDH + lhal * 8) * 2);
    const uint32_t loB = (uint32_t)((lrow * BLDH + wc * 64 + lhal * 8) * 2);

    // copy-slot mapping
    const int ar = tid >> 3;            // A rows 0..31 (+32*j)
    const int ac = (tid & 7) << 2;      // A cols (floats/halves idx) 0,4..28

    float4 areg[4];

    auto ldgA = [&](int i) {
        const float* Af = (const float*)Ap;
        const float* Ab = Af + (size_t)row0 * KD + i * 32;
#pragma unroll
        for (int j = 0; j < 4; j++)
            areg[j] = *(const float4*)(Ab + (size_t)(ar + 32 * j) * KD + ac);
    };
    auto stsA = [&](__half* As) {
#pragma unroll
        for (int j = 0; j < 4; j++) {
            uint2 o = make_uint2(pkh2(areg[j].x, areg[j].y),
                                 pkh2(areg[j].z, areg[j].w));
            *(uint2*)(As + (ar + 32 * j) * ALDH + ac) = o;
        }
    };
    auto cpA = [&](int i, __half* As) {
        const __half* Ah = (const __half*)Ap;
#pragma unroll
        for (int j = 0; j < 2; j++) {
            int idx = tid + j * 256;
            int r   = idx >> 2;
            int sg  = (idx & 3) << 3;
            CP16(smem_u32(As + r * ALDH + sg),
                 Ah + (size_t)(row0 + r) * KD + i * 32 + sg);
        }
    };
    auto cpB = [&](int i, __half* Bs) {
#pragma unroll
        for (int j = 0; j < 2; j++) {
            int idx = tid + j * 256;
            int r   = idx >> 4;
            int sg  = (idx & 15) << 3;
            CP16(smem_u32(Bs + r * BLDH + sg),
                 Bt + (size_t)(i * 32 + r) * NOUT + n0 + sg);
        }
    };

    // Prologue: chunk 0 into stage 0
    {
        __half* As0 = sh;
        __half* Bs0 = sh + AHALF;
        if (AASYNC) cpA(0, As0); else ldgA(0);
        cpB(0, Bs0);
        CP_COMMIT();
    }

#pragma unroll
    for (int i = 0; i < NCH; i++) {
        __half* As = sh + (i & 1) * STGH;
        __half* Bs = As + AHALF;
        if (!AASYNC) stsA(As);
        if (i + 1 < NCH) {
            __half* Asn = sh + ((i + 1) & 1) * STGH;
            if (AASYNC) cpA(i + 1, Asn);
            cpB(i + 1, Asn + AHALF);
            CP_COMMIT();
            if (!AASYNC) ldgA(i + 1);
            CP_WAIT(1);
        } else {
            CP_WAIT(0);
        }
        __syncthreads();

        const uint32_t uA = smem_u32(As) + loA;
        const uint32_t uB = smem_u32(Bs) + loB;
#pragma unroll
        for (int kk = 0; kk < 32; kk += 16) {
            uint32_t af[2][4], bf[4][4];
#pragma unroll
            for (int u = 0; u < 2; u++)
                ldmx4(af[u], uA + (uint32_t)((u * 16 * ALDH + kk) * 2));
#pragma unroll
            for (int v = 0; v < 4; v++)
                ldmx4t(bf[v], uB + (uint32_t)((kk * BLDH + v * 16) * 2));
#pragma unroll
            for (int u = 0; u < 2; u++)
#pragma unroll
                for (int v = 0; v < 4; v++) {
                    mma16816(acc[u][v * 2 + 0], af[u], bf[v] + 0);
                    mma16816(acc[u][v * 2 + 1], af[u], bf[v] + 2);
                }
        }
        __syncthreads();
    }

    // m16n8 acc lane map: tg = lane>>2 (row in 0..7), tt = lane&3 (col pair)
    const int tg = lane >> 2;
    const int tt = lane & 3;

    if (!EPI) {
#pragma unroll
        for (int u = 0; u < 2; u++)
#pragma unroll
            for (int w = 0; w < 8; w++) {
                int mm = row0 + wr * 32 + u * 16 + tg;
                int nn = n0 + wc * 64 + w * 8 + tt * 2;
                *(float2*)(Cout + (size_t)mm * NOUT + nn) =
                    make_float2(acc[u][w][0], acc[u][w][1]);
                *(float2*)(Cout + (size_t)(mm + 8) * NOUT + nn) =
                    make_float2(acc[u][w][2], acc[u][w][3]);
            }
    } else {
        float* Cs = (float*)smraw;   // 128 x 132 fp32
#pragma unroll
        for (int u = 0; u < 2; u++)
#pragma unroll
            for (int w = 0; w < 8; w++) {
                int mm = wr * 32 + u * 16 + tg;
                int nn = wc * 64 + w * 8 + tt * 2;
                *(float2*)(Cs + mm * 132 + nn) =
                    make_float2(acc[u][w][0], acc[u][w][1]);
                *(float2*)(Cs + (mm + 8) * 132 + nn) =
                    make_float2(acc[u][w][2], acc[u][w][3]);
            }
        __syncthreads();

        float b1f[4], w2f[4];
#pragma unroll
        for (int q = 0; q < 4; q++) {
            int gcol = n0 + lane + q * 32;
            b1f[q] = b1v[gcol];
            w2f[q] = W2v[gcol];
        }
#pragma unroll
        for (int rr = 0; rr < 16; rr++) {
            int r = warp * 16 + rr;
            float p = 0.f;
#pragma unroll
            for (int q = 0; q < 4; q++) {
                float x = Cs[r * 132 + lane + q * 32] + b1f[q];
                float h = 0.5f * x * (1.f + erff(x * 0.7071067811865476f));
                p = fmaf(h, w2f[q], p);
            }
#pragma unroll
            for (int off = 16; off > 0; off >>= 1)
                p += __shfl_xor_sync(0xffffffffu, p, off);
            if (lane == 0)
                g_plog[(size_t)(row0 + r) * NBLK_ + blockIdx.y] = p;
        }
    }
}

// ---------------------------------------------------------------------------
// LN pass: adds bias, LayerNorms in place. y=0 -> g_v (+g_rv), y=1 -> g_a.
// ---------------------------------------------------------------------------
__global__ __launch_bounds__(256) void ln_kernel(
    const float* __restrict__ bv, const float* __restrict__ ba)
{
    __shared__ float redS[8], redQ[8], bc2[2];
    const int row = blockIdx.x;
    const int d   = threadIdx.x;
    float* buf = blockIdx.y ? g_a : g_v;
    const float* bias = blockIdx.y ? ba : bv;

    float x = buf[(size_t)row * DM_ + d] + bias[d];
    float s = x, q = x * x;
#pragma unroll
    for (int off = 16; off > 0; off >>= 1) {
        s += __shfl_xor_sync(0xffffffffu, s, off);
        q += __shfl_xor_sync(0xffffffffu, q, off);
    }
    int lane = d & 31, warp = d >> 5;
    if (lane == 0) { redS[warp] = s; redQ[warp] = q; }
    __syncthreads();
    if (d == 0) {
        float ts = 0.f, tq = 0.f;
#pragma unroll
        for (int k = 0; k < 8; k++) { ts += redS[k]; tq += redQ[k]; }
        float mu  = ts * (1.f / 256.f);
        float var = fmaxf(tq * (1.f / 256.f) - mu * mu, 0.f);
        bc2[0] = mu;
        bc2[1] = rsqrtf(var + 1e-5f);
        if (blockIdx.y == 0) {
            float l2 = sqrtf(256.f * var) * bc2[1];
            g_rv[row] = 1.f / fmaxf(l2, 1e-8f);
        }
    }
    __syncthreads();
    buf[(size_t)row * DM_ + d] = (x - bc2[0]) * bc2[1];
}

// ---------------------------------------------------------------------------
// ctx: temporal shift + causal 6-tap window avg + l2 norms + build X (fp16).
// 4 rows/block, 64 threads/row, float4 per thread. center==t (delta in (2,6)).
// ---------------------------------------------------------------------------
__global__ __launch_bounds__(256) void ctx_kernel(const float* __restrict__ theta)
{
    __shared__ float red2[4][2];
    const int tid = threadIdx.x;
    const int rl  = tid >> 6;
    const int q   = tid & 63;
    const int row = blockIdx.x * 4 + rl;
    const int b   = row >> 11;
    const int t   = row & 2047;

    float th    = fminf(fmaxf(theta[0], -12.f), 12.f);
    float delta = 2.f + 4.f / (1.f + expf(-th));
    float nf    = floorf(delta);
    float alpha = delta - nf;
    int   ni    = (int)nf;

    const int lo = max(0, t - 5);
    const float inv_cnt = 1.f / (float)(t - lo + 1);

    const float* ab = g_a + (size_t)b * T_ * DM_;
    float4 acc = {0.f, 0.f, 0.f, 0.f};
    for (int tau = lo; tau <= t; tau++) {
        int i0 = min(max(tau - ni, 0), T_ - 1);
        int i1 = min(i0 + 1, T_ - 1);
        float4 x0 = *(const float4*)(ab + (size_t)i0 * DM_ + q * 4);
        float4 x1 = *(const float4*)(ab + (size_t)i1 * DM_ + q * 4);
        acc.x += (1.f - alpha) * x0.x + alpha * x1.x;
        acc.y += (1.f - alpha) * x0.y + alpha * x1.y;
        acc.z += (1.f - alpha) * x0.z + alpha * x1.z;
        acc.w += (1.f - alpha) * x0.w + alpha * x1.w;
    }
    float4 ac = {acc.x * inv_cnt, acc.y * inv_cnt, acc.z * inv_cnt, acc.w * inv_cnt};

    float ss = ac.x * ac.x + ac.y * ac.y + ac.z * ac.z + ac.w * ac.w;
#pragma unroll
    for (int off = 16; off > 0; off >>= 1)
        ss += __shfl_xor_sync(0xffffffffu, ss, off);
    const int wp = tid >> 5;
    if ((tid & 31) == 0) red2[wp >> 1][wp & 1] = ss;
    __syncthreads();
    float tot = red2[rl][0] + red2[rl][1];
    float ra  = 1.f / fmaxf(sqrtf(tot), 1e-8f);

    float4 vv = *(const float4*)(g_v + (size_t)row * DM_ + q * 4);
    float rv  = g_rv[row];

    *(float4*)(g_actx + (size_t)row * DM_ + q * 4) = ac;

    float vnx = vv.x * rv, vny = vv.y * rv, vnz = vv.z * rv, vnw = vv.w * rv;
    float anx = ac.x * ra, any_ = ac.y * ra, anz = ac.z * ra, anw = ac.w * ra;

    __half* xr = g_Xh + (size_t)row * XDIM_;
    *(uint2*)(xr + q * 4) =
        make_uint2(pkh2(anx, any_), pkh2(anz, anw));
    *(uint2*)(xr + DM_ + q * 4) =
        make_uint2(pkh2(vnx, vny), pkh2(vnz, vnw));
    *(uint2*)(xr + 2 * DM_ + q * 4) =
        make_uint2(pkh2(anx * vnx, any_ * vny), pkh2(anz * vnz, anw * vnw));
}

// ---------------------------------------------------------------------------
// out: finish logit, gate, mix. float4 per thread.
// ---------------------------------------------------------------------------
__global__ __launch_bounds__(256) void out_kernel(
    const float* __restrict__ b2, float* __restrict__ out)
{
    const int idx = blockIdx.x * 256 + threadIdx.x;   // over R_*64 float4s
    const int row = idx >> 6;
    const int c4  = (idx & 63) << 2;
    float s = b2[0];
#pragma unroll
    for (int k = 0; k < NBLK_; k++) s += g_plog[(size_t)row * NBLK_ + k];
    s = fminf(fmaxf(s, -12.f), 12.f);
    float g = 1.f / (1.f + expf(-s));
    g = fminf(fmaxf(g, 0.05f), 0.95f);
    float4 ac = *(const float4*)(g_actx + (size_t)row * DM_ + c4);
    float4 vv = *(const float4*)(g_v + (size_t)row * DM_ + c4);
    float4 o  = {g * ac.x + (1.f - g) * vv.x, g * ac.y + (1.f - g) * vv.y,
                 g * ac.z + (1.f - g) * vv.z, g * ac.w + (1.f - g) * vv.w};
    *(float4*)(out + (size_t)row * DM_ + c4) = o;
}

// ---------------------------------------------------------------------------
extern "C" void kernel_launch(void* const* d_in, const int* in_sizes, int n_in,
                              void* d_out, int out_size)
{
    const float* video = (const float*)d_in[0];
    const float* audio = (const float*)d_in[1];
    const float* Wv    = (const float*)d_in[2];
    const float* bv    = (const float*)d_in[3];
    const float* Wa    = (const float*)d_in[4];
    const float* ba    = (const float*)d_in[5];
    const float* theta = (const float*)d_in[6];
    const float* W1    = (const float*)d_in[7];
    const float* b1    = (const float*)d_in[8];
    const float* W2    = (const float*)d_in[9];
    const float* b2    = (const float*)d_in[10];
    float* out = (float*)d_out;

    float *gv, *ga;
    __half *gxh, *wv, *wa, *w1;
    cudaGetSymbolAddress((void**)&gv,  g_v);
    cudaGetSymbolAddress((void**)&ga,  g_a);
    cudaGetSymbolAddress((void**)&gxh, g_Xh);
    cudaGetSymbolAddress((void**)&wv,  g_wv);
    cudaGetSymbolAddress((void**)&wa,  g_wa);
    cudaGetSymbolAddress((void**)&w1,  g_w1);

    const int gsm = 2 * STGH * sizeof(__half);        // 37888 B
    const int msm = 128 * 132 * sizeof(float);        // 67584 B (epilogue C)
    cudaFuncSetAttribute(gemm_m<VDIM_/32, DM_, false, false>,
        cudaFuncAttributeMaxDynamicSharedMemorySize, gsm);
    cudaFuncSetAttribute(gemm_m<ADIM_/32, DM_, false, false>,
        cudaFuncAttributeMaxDynamicSharedMemorySize, gsm);
    cudaFuncSetAttribute(gemm_m<XDIM_/32, HID_, true, true>,
        cudaFuncAttributeMaxDynamicSharedMemorySize, msm);

    // weight prep (fp32 -> fp16)
    prep_wh<<<(VDIM_*DM_/4 + 255)/256, 256>>>(Wv, wv, VDIM_*DM_/4);
    prep_wh<<<(ADIM_*DM_/4 + 255)/256, 256>>>(Wa, wa, ADIM_*DM_/4);
    prep_wh<<<(XDIM_*HID_/4 + 255)/256, 256>>>(W1, w1, XDIM_*HID_/4);

    gemm_m<VDIM_/32, DM_, false, false><<<dim3(R_/128, 2), 256, gsm>>>(
        video, wv, nullptr, nullptr, gv);
    gemm_m<ADIM_/32, DM_, false, false><<<dim3(R_/128, 2), 256, gsm>>>(
        audio, wa, nullptr, nullptr, ga);
    ln_kernel<<<dim3(R_, 2), 256>>>(bv, ba);
    ctx_kernel<<<R_/4, 256>>>(theta);
    gemm_m<XDIM_/32, HID_, true, true><<<dim3(R_/128, NBLK_), 256, msm>>>(
        gxh, w1, b1, W2, nullptr);
    out_kernel<<<(R_*64)/256, 256>>>(b2, out);
}

// round 12
// speedup vs baseline: 1.0813x; 1.0273x over previous
#include <cuda_runtime.h>
#include <cuda_fp16.h>
#include <math.h>
#include <stdint.h>

// Problem constants
#define B_    8
#define T_    2048
#define R_    (B_*T_)     // 16384 rows
#define VDIM_ 1024
#define ADIM_ 768
#define DM_   256
#define HID_  1024
#define XDIM_ 768         // 3*DM
#define NBLK_ 8           // HID / 128 column blocks for gate GEMM

// Scratch (__device__ globals; allocation-free rule)
__device__ __align__(16) float g_v[R_*DM_];      // raw video proj -> LN'd in place
__device__ float g_rv[R_];                       // 1/max(||v_row||,eps)
__device__ __align__(16) float g_a[R_*DM_];      // raw audio proj -> LN'd in place
__device__ __align__(16) float g_actx[R_*DM_];   // audio context (full precision)
__device__ __align__(16) __half g_Xh[R_*XDIM_];  // [an, vn, an*vn] in fp16
__device__ float g_plog[R_*NBLK_];               // partial logits
// fp16 weights
__device__ __align__(16) __half g_wv[VDIM_*DM_];
__device__ __align__(16) __half g_wa[ADIM_*DM_];
__device__ __align__(16) __half g_w1[XDIM_*HID_];

__device__ __forceinline__ uint32_t smem_u32(const void* p) {
    uint32_t a;
    asm("{ .reg .u64 t; cvta.to.shared.u64 t, %1; cvt.u32.u64 %0, t; }"
        : "=r"(a) : "l"(p));
    return a;
}
#define CP16(dst_u32, src_ptr) \
    asm volatile("cp.async.cg.shared.global [%0], [%1], 16;" \
                 :: "r"(dst_u32), "l"(src_ptr) : "memory")
#define CP_COMMIT() asm volatile("cp.async.commit_group;" ::: "memory")
#define CP_WAIT(n)  asm volatile("cp.async.wait_group %0;" :: "n"(n) : "memory")

__device__ __forceinline__ uint32_t pkh2(float a, float b) {
    __half2 h = __floats2half2_rn(a, b);
    return *reinterpret_cast<uint32_t*>(&h);
}
__device__ __forceinline__ void ldmx4(uint32_t* r, uint32_t addr) {
    asm volatile("ldmatrix.sync.aligned.m8n8.x4.shared.b16 {%0,%1,%2,%3}, [%4];"
        : "=r"(r[0]), "=r"(r[1]), "=r"(r[2]), "=r"(r[3]) : "r"(addr));
}
__device__ __forceinline__ void ldmx4t(uint32_t* r, uint32_t addr) {
    asm volatile("ldmatrix.sync.aligned.m8n8.x4.trans.shared.b16 {%0,%1,%2,%3}, [%4];"
        : "=r"(r[0]), "=r"(r[1]), "=r"(r[2]), "=r"(r[3]) : "r"(addr));
}
__device__ __forceinline__ void mma16816(float* d, const uint32_t* a,
                                         const uint32_t* b) {
    asm volatile(
        "mma.sync.aligned.m16n8k16.row.col.f32.f16.f16.f32 "
        "{%0,%1,%2,%3}, {%4,%5,%6,%7}, {%8,%9}, {%0,%1,%2,%3};"
        : "+f"(d[0]), "+f"(d[1]), "+f"(d[2]), "+f"(d[3])
        : "r"(a[0]), "r"(a[1]), "r"(a[2]), "r"(a[3]), "r"(b[0]), "r"(b[1]));
}

// ---------------------------------------------------------------------------
// prep: convert all three weight matrices fp32 -> fp16 in ONE launch.
// ---------------------------------------------------------------------------
#define PW1 (VDIM_*DM_/4)                 // 65536 float4s
#define PW2 (PW1 + ADIM_*DM_/4)           // +49152
#define PW3 (PW2 + XDIM_*HID_/4)          // +196608 = 311296
__global__ __launch_bounds__(256) void prep_all(
    const float* __restrict__ Wv, const float* __restrict__ Wa,
    const float* __restrict__ W1)
{
    int i = blockIdx.x * 256 + threadIdx.x;
    const float* src;
    __half* dst;
    int off;
    if (i < PW1)      { src = Wv; dst = g_wv; off = i; }
    else if (i < PW2) { src = Wa; dst = g_wa; off = i - PW1; }
    else if (i < PW3) { src = W1; dst = g_w1; off = i - PW2; }
    else return;
    float4 v = ((const float4*)src)[off];
    uint2 o = make_uint2(pkh2(v.x, v.y), pkh2(v.z, v.w));
    *(uint2*)(dst + (size_t)off * 4) = o;
}

// ---------------------------------------------------------------------------
// FP16 raw-mma GEMM body (device function): C = A[R x KD] @ Bt[KD x NOUT],
// CTA tile 128x128, BK = 32 or 64, 8 warps (4x2), warp tile 32x64,
// ldmatrix.x4(+trans) + mma.sync.m16n8k16, 2-stage cp.async pipeline.
// AASYNC: A already fp16 -> cp.async. Else LDG fp32 -> cvt -> STS (BK=32 only).
// EPI=0: raw fp32 C to Cout. EPI=1: mlp epilogue (bias + exact gelu . W2).
// ---------------------------------------------------------------------------
#define BLDH 136                     // B smem leading dim (halves): 68-word rows

template<int NCH, int BK, int NOUT, bool AASYNC, bool EPI>
__device__ __forceinline__ void gemm_body(
    char* smraw,
    const void* __restrict__ Ap, const __half* __restrict__ Bt,
    const float* __restrict__ b1v, const float* __restrict__ W2v,
    float* __restrict__ Cout)
{
    constexpr int ALDH  = BK + 8;            // 40 or 72 halves (conflict-free)
    constexpr int AHALF = 128 * ALDH;
    constexpr int STGH  = AHALF + BK * BLDH;

    __half* sh = (__half*)smraw;
    const int tid  = threadIdx.x;
    const int lane = tid & 31;
    const int warp = tid >> 5;
    const int wr   = warp >> 1;         // 0..3 (32-row block)
    const int wc   = warp & 1;          // 0..1 (64-col block)
    const int row0 = blockIdx.x * 128;
    const int n0   = blockIdx.y * 128;
    const int KD   = NCH * BK;

    float acc[2][8][4];
#pragma unroll
    for (int u = 0; u < 2; u++)
#pragma unroll
        for (int w = 0; w < 8; w++)
#pragma unroll
            for (int x = 0; x < 4; x++) acc[u][w][x] = 0.f;

    const int lrow = lane & 15;
    const int lhal = lane >> 4;
    const uint32_t loA = (uint32_t)(((wr * 32 + lrow) * ALDH + lhal * 8) * 2);
    const uint32_t loB = (uint32_t)((lrow * BLDH + wc * 64 + lhal * 8) * 2);

    // sync-A (BK=32) copy mapping
    const int ar = tid >> 3;            // rows 0..31 (+32*j)
    const int ac = (tid & 7) << 2;

    float4 areg[4];

    auto ldgA = [&](int i) {
        const float* Af = (const float*)Ap;
        const float* Ab = Af + (size_t)row0 * KD + i * BK;
#pragma unroll
        for (int j = 0; j < 4; j++)
            areg[j] = *(const float4*)(Ab + (size_t)(ar + 32 * j) * KD + ac);
    };
    auto stsA = [&](__half* As) {
#pragma unroll
        for (int j = 0; j < 4; j++) {
            uint2 o = make_uint2(pkh2(areg[j].x, areg[j].y),
                                 pkh2(areg[j].z, areg[j].w));
            *(uint2*)(As + (ar + 32 * j) * ALDH + ac) = o;
        }
    };
    auto cpA = [&](int i, __half* As) {
        const __half* Ah = (const __half*)Ap;
        constexpr int SEGS = BK / 8;            // 16B segments per row
        constexpr int NCP  = 128 * SEGS / 256;  // per-thread CP16 count
#pragma unroll
        for (int j = 0; j < NCP; j++) {
            int idx = tid + j * 256;
            int r, sg;
            if (BK == 64) { r = idx >> 3; sg = (idx & 7) << 3; }
            else          { r = idx >> 2; sg = (idx & 3) << 3; }
            CP16(smem_u32(As + r * ALDH + sg),
                 Ah + (size_t)(row0 + r) * KD + i * BK + sg);
        }
    };
    auto cpB = [&](int i, __half* Bs) {
        constexpr int NCP = BK * 16 / 256;
#pragma unroll
        for (int j = 0; j < NCP; j++) {
            int idx = tid + j * 256;
            int r   = idx >> 4;
            int sg  = (idx & 15) << 3;
            CP16(smem_u32(Bs + r * BLDH + sg),
                 Bt + (size_t)(i * BK + r) * NOUT + n0 + sg);
        }
    };

    // Prologue: chunk 0 into stage 0
    {
        __half* As0 = sh;
        __half* Bs0 = sh + AHALF;
        if (AASYNC) cpA(0, As0); else ldgA(0);
        cpB(0, Bs0);
        CP_COMMIT();
    }

#pragma unroll
    for (int i = 0; i < NCH; i++) {
        __half* As = sh + (i & 1) * STGH;
        __half* Bs = As + AHALF;
        if (!AASYNC) stsA(As);
        if (i + 1 < NCH) {
            __half* Asn = sh + ((i + 1) & 1) * STGH;
            if (AASYNC) cpA(i + 1, Asn);
            cpB(i + 1, Asn + AHALF);
            CP_COMMIT();
            if (!AASYNC) ldgA(i + 1);
            CP_WAIT(1);
        } else {
            CP_WAIT(0);
        }
        __syncthreads();

        const uint32_t uA = smem_u32(As) + loA;
        const uint32_t uB = smem_u32(Bs) + loB;
#pragma unroll
        for (int kk = 0; kk < BK; kk += 16) {
            uint32_t af[2][4], bf[4][4];
#pragma unroll
            for (int u = 0; u < 2; u++)
                ldmx4(af[u], uA + (uint32_t)((u * 16 * ALDH + kk) * 2));
#pragma unroll
            for (int v = 0; v < 4; v++)
                ldmx4t(bf[v], uB + (uint32_t)((kk * BLDH + v * 16) * 2));
#pragma unroll
            for (int u = 0; u < 2; u++)
#pragma unroll
                for (int v = 0; v < 4; v++) {
                    mma16816(acc[u][v * 2 + 0], af[u], bf[v] + 0);
                    mma16816(acc[u][v * 2 + 1], af[u], bf[v] + 2);
                }
        }
        __syncthreads();
    }

    const int tg = lane >> 2;
    const int tt = lane & 3;

    if (!EPI) {
#pragma unroll
        for (int u = 0; u < 2; u++)
#pragma unroll
            for (int w = 0; w < 8; w++) {
                int mm = row0 + wr * 32 + u * 16 + tg;
                int nn = n0 + wc * 64 + w * 8 + tt * 2;
                *(float2*)(Cout + (size_t)mm * NOUT + nn) =
                    make_float2(acc[u][w][0], acc[u][w][1]);
                *(float2*)(Cout + (size_t)(mm + 8) * NOUT + nn) =
                    make_float2(acc[u][w][2], acc[u][w][3]);
            }
    } else {
        float* Cs = (float*)smraw;   // 128 x 132 fp32
#pragma unroll
        for (int u = 0; u < 2; u++)
#pragma unroll
            for (int w = 0; w < 8; w++) {
                int mm = wr * 32 + u * 16 + tg;
                int nn = wc * 64 + w * 8 + tt * 2;
                *(float2*)(Cs + mm * 132 + nn) =
                    make_float2(acc[u][w][0], acc[u][w][1]);
                *(float2*)(Cs + (mm + 8) * 132 + nn) =
                    make_float2(acc[u][w][2], acc[u][w][3]);
            }
        __syncthreads();

        float b1f[4], w2f[4];
#pragma unroll
        for (int q = 0; q < 4; q++) {
            int gcol = n0 + lane + q * 32;
            b1f[q] = b1v[gcol];
            w2f[q] = W2v[gcol];
        }
#pragma unroll
        for (int rr = 0; rr < 16; rr++) {
            int r = warp * 16 + rr;
            float p = 0.f;
#pragma unroll
            for (int q = 0; q < 4; q++) {
                float x = Cs[r * 132 + lane + q * 32] + b1f[q];
                float h = 0.5f * x * (1.f + erff(x * 0.7071067811865476f));
                p = fmaf(h, w2f[q], p);
            }
#pragma unroll
            for (int off = 16; off > 0; off >>= 1)
                p += __shfl_xor_sync(0xffffffffu, p, off);
            if (lane == 0)
                g_plog[(size_t)(row0 + r) * NBLK_ + blockIdx.y] = p;
        }
    }
}

// ---------------------------------------------------------------------------
// Fused projection GEMMs: z=0 video (K=1024), z=1 audio (K=768). One launch
// of 512 CTAs fills the 296 co-residency slots far better than 2x256.
// ---------------------------------------------------------------------------
__global__ __launch_bounds__(256, 2) void gemm_proj(
    const float* __restrict__ video, const float* __restrict__ audio)
{
    extern __shared__ __align__(16) char smraw[];
    if (blockIdx.z == 0)
        gemm_body<VDIM_/32, 32, DM_, false, false>(
            smraw, video, g_wv, nullptr, nullptr, g_v);
    else
        gemm_body<ADIM_/32, 32, DM_, false, false>(
            smraw, audio, g_wa, nullptr, nullptr, g_a);
}

// ---------------------------------------------------------------------------
// mlp GEMM: BK=64 (half the barriers), pure cp.async A, fused epilogue.
// ---------------------------------------------------------------------------
__global__ __launch_bounds__(256, 2) void gemm_mlp(
    const float* __restrict__ b1v, const float* __restrict__ W2v)
{
    extern __shared__ __align__(16) char smraw[];
    gemm_body<XDIM_/64, 64, HID_, true, true>(
        smraw, g_Xh, g_w1, b1v, W2v, nullptr);
}

// ---------------------------------------------------------------------------
// LN pass: adds bias, LayerNorms in place. y=0 -> g_v (+g_rv), y=1 -> g_a.
// ---------------------------------------------------------------------------
__global__ __launch_bounds__(256) void ln_kernel(
    const float* __restrict__ bv, const float* __restrict__ ba)
{
    __shared__ float redS[8], redQ[8], bc2[2];
    const int row = blockIdx.x;
    const int d   = threadIdx.x;
    float* buf = blockIdx.y ? g_a : g_v;
    const float* bias = blockIdx.y ? ba : bv;

    float x = buf[(size_t)row * DM_ + d] + bias[d];
    float s = x, q = x * x;
#pragma unroll
    for (int off = 16; off > 0; off >>= 1) {
        s += __shfl_xor_sync(0xffffffffu, s, off);
        q += __shfl_xor_sync(0xffffffffu, q, off);
    }
    int lane = d & 31, warp = d >> 5;
    if (lane == 0) { redS[warp] = s; redQ[warp] = q; }
    __syncthreads();
    if (d == 0) {
        float ts = 0.f, tq = 0.f;
#pragma unroll
        for (int k = 0; k < 8; k++) { ts += redS[k]; tq += redQ[k]; }
        float mu  = ts * (1.f / 256.f);
        float var = fmaxf(tq * (1.f / 256.f) - mu * mu, 0.f);
        bc2[0] = mu;
        bc2[1] = rsqrtf(var + 1e-5f);
        if (blockIdx.y == 0) {
            float l2 = sqrtf(256.f * var) * bc2[1];
            g_rv[row] = 1.f / fmaxf(l2, 1e-8f);
        }
    }
    __syncthreads();
    buf[(size_t)row * DM_ + d] = (x - bc2[0]) * bc2[1];
}

// ---------------------------------------------------------------------------
// ctx: temporal shift + causal 6-tap window avg + l2 norms + build X (fp16).
// 4 rows/block, 64 threads/row, float4 per thread. center==t (delta in (2,6)).
// ---------------------------------------------------------------------------
__global__ __launch_bounds__(256) void ctx_kernel(const float* __restrict__ theta)
{
    __shared__ float red2[4][2];
    const int tid = threadIdx.x;
    const int rl  = tid >> 6;
    const int q   = tid & 63;
    const int row = blockIdx.x * 4 + rl;
    const int b   = row >> 11;
    const int t   = row & 2047;

    float th    = fminf(fmaxf(theta[0], -12.f), 12.f);
    float delta = 2.f + 4.f / (1.f + expf(-th));
    float nf    = floorf(delta);
    float alpha = delta - nf;
    int   ni    = (int)nf;

    const int lo = max(0, t - 5);
    const float inv_cnt = 1.f / (float)(t - lo + 1);

    const float* ab = g_a + (size_t)b * T_ * DM_;
    float4 acc = {0.f, 0.f, 0.f, 0.f};
    for (int tau = lo; tau <= t; tau++) {
        int i0 = min(max(tau - ni, 0), T_ - 1);
        int i1 = min(i0 + 1, T_ - 1);
        float4 x0 = *(const float4*)(ab + (size_t)i0 * DM_ + q * 4);
        float4 x1 = *(const float4*)(ab + (size_t)i1 * DM_ + q * 4);
        acc.x += (1.f - alpha) * x0.x + alpha * x1.x;
        acc.y += (1.f - alpha) * x0.y + alpha * x1.y;
        acc.z += (1.f - alpha) * x0.z + alpha * x1.z;
        acc.w += (1.f - alpha) * x0.w + alpha * x1.w;
    }
    float4 ac = {acc.x * inv_cnt, acc.y * inv_cnt, acc.z * inv_cnt, acc.w * inv_cnt};

    float ss = ac.x * ac.x + ac.y * ac.y + ac.z * ac.z + ac.w * ac.w;
#pragma unroll
    for (int off = 16; off > 0; off >>= 1)
        ss += __shfl_xor_sync(0xffffffffu, ss, off);
    const int wp = tid >> 5;
    if ((tid & 31) == 0) red2[wp >> 1][wp & 1] = ss;
    __syncthreads();
    float tot = red2[rl][0] + red2[rl][1];
    float ra  = 1.f / fmaxf(sqrtf(tot), 1e-8f);

    float4 vv = *(const float4*)(g_v + (size_t)row * DM_ + q * 4);
    float rv  = g_rv[row];

    *(float4*)(g_actx + (size_t)row * DM_ + q * 4) = ac;

    float vnx = vv.x * rv, vny = vv.y * rv, vnz = vv.z * rv, vnw = vv.w * rv;
    float anx = ac.x * ra, any_ = ac.y * ra, anz = ac.z * ra, anw = ac.w * ra;

    __half* xr = g_Xh + (size_t)row * XDIM_;
    *(uint2*)(xr + q * 4) =
        make_uint2(pkh2(anx, any_), pkh2(anz, anw));
    *(uint2*)(xr + DM_ + q * 4) =
        make_uint2(pkh2(vnx, vny), pkh2(vnz, vnw));
    *(uint2*)(xr + 2 * DM_ + q * 4) =
        make_uint2(pkh2(anx * vnx, any_ * vny), pkh2(anz * vnz, anw * vnw));
}

// ---------------------------------------------------------------------------
// out: finish logit, gate, mix. float4 per thread.
// ---------------------------------------------------------------------------
__global__ __launch_bounds__(256) void out_kernel(
    const float* __restrict__ b2, float* __restrict__ out)
{
    const int idx = blockIdx.x * 256 + threadIdx.x;   // over R_*64 float4s
    const int row = idx >> 6;
    const int c4  = (idx & 63) << 2;
    float s = b2[0];
#pragma unroll
    for (int k = 0; k < NBLK_; k++) s += g_plog[(size_t)row * NBLK_ + k];
    s = fminf(fmaxf(s, -12.f), 12.f);
    float g = 1.f / (1.f + expf(-s));
    g = fminf(fmaxf(g, 0.05f), 0.95f);
    float4 ac = *(const float4*)(g_actx + (size_t)row * DM_ + c4);
    float4 vv = *(const float4*)(g_v + (size_t)row * DM_ + c4);
    float4 o  = {g * ac.x + (1.f - g) * vv.x, g * ac.y + (1.f - g) * vv.y,
                 g * ac.z + (1.f - g) * vv.z, g * ac.w + (1.f - g) * vv.w};
    *(float4*)(out + (size_t)row * DM_ + c4) = o;
}

// ---------------------------------------------------------------------------
extern "C" void kernel_launch(void* const* d_in, const int* in_sizes, int n_in,
                              void* d_out, int out_size)
{
    const float* video = (const float*)d_in[0];
    const float* audio = (const float*)d_in[1];
    const float* Wv    = (const float*)d_in[2];
    const float* bv    = (const float*)d_in[3];
    const float* Wa    = (const float*)d_in[4];
    const float* ba    = (const float*)d_in[5];
    const float* theta = (const float*)d_in[6];
    const float* W1    = (const float*)d_in[7];
    const float* b1    = (const float*)d_in[8];
    const float* W2    = (const float*)d_in[9];
    const float* b2    = (const float*)d_in[10];
    float* out = (float*)d_out;

    // smem sizes: proj stage (BK=32): 128*40 + 32*136 = 9472 halves = 18944 B
    //             mlp  stage (BK=64): 128*72 + 64*136 = 17920 halves = 35840 B
    const int gsm = 2 * 18944;     // 37888 B
    const int mst = 2 * 35840;     // 71680 B (>= 67584 B epilogue Cs)
    cudaFuncSetAttribute(gemm_proj,
        cudaFuncAttributeMaxDynamicSharedMemorySize, gsm);
    cudaFuncSetAttribute(gemm_mlp,
        cudaFuncAttributeMaxDynamicSharedMemorySize, mst);

    prep_all<<<(PW3 + 255)/256, 256>>>(Wv, Wa, W1);
    gemm_proj<<<dim3(R_/128, 2, 2), 256, gsm>>>(video, audio);
    ln_kernel<<<dim3(R_, 2), 256>>>(bv, ba);
    ctx_kernel<<<R_/4, 256>>>(theta);
    gemm_mlp<<<dim3(R_/128, NBLK_), 256, mst>>>(b1, W2);
    out_kernel<<<(R_*64)/256, 256>>>(b2, out);
}

// round 13
// speedup vs baseline: 1.2208x; 1.1290x over previous
#include <cuda_runtime.h>
#include <cuda_fp16.h>
#include <math.h>
#include <stdint.h>

// Problem constants
#define B_    8
#define T_    2048
#define R_    (B_*T_)     // 16384 rows
#define VDIM_ 1024
#define ADIM_ 768
#define DM_   256
#define HID_  1024
#define XDIM_ 768         // 3*DM
#define NBLK_ 8           // HID / 128 column blocks for gate GEMM

// Scratch (__device__ globals; allocation-free rule)
__device__ __align__(16) float g_v[R_*DM_];      // LN'd video proj
__device__ float g_rv[R_];                       // 1/max(||v_row||,eps)
__device__ __align__(16) float g_a[R_*DM_];      // LN'd audio proj
__device__ __align__(16) float g_actx[R_*DM_];   // audio context
__device__ __align__(16) __half g_Xh[R_*XDIM_];  // [an, vn, an*vn] fp16
__device__ float g_plog[R_*NBLK_];               // partial logits
// fp16 weights
__device__ __align__(16) __half g_wv[VDIM_*DM_];
__device__ __align__(16) __half g_wa[ADIM_*DM_];
__device__ __align__(16) __half g_w1[XDIM_*HID_];

__device__ __forceinline__ uint32_t smem_u32(const void* p) {
    uint32_t a;
    asm("{ .reg .u64 t; cvta.to.shared.u64 t, %1; cvt.u32.u64 %0, t; }"
        : "=r"(a) : "l"(p));
    return a;
}
#define CP16(dst_u32, src_ptr) \
    asm volatile("cp.async.cg.shared.global [%0], [%1], 16;" \
                 :: "r"(dst_u32), "l"(src_ptr) : "memory")
#define CP_COMMIT() asm volatile("cp.async.commit_group;" ::: "memory")
#define CP_WAIT(n)  asm volatile("cp.async.wait_group %0;" :: "n"(n) : "memory")

__device__ __forceinline__ uint32_t pkh2(float a, float b) {
    __half2 h = __floats2half2_rn(a, b);
    return *reinterpret_cast<uint32_t*>(&h);
}
__device__ __forceinline__ void ldmx4(uint32_t* r, uint32_t addr) {
    asm volatile("ldmatrix.sync.aligned.m8n8.x4.shared.b16 {%0,%1,%2,%3}, [%4];"
        : "=r"(r[0]), "=r"(r[1]), "=r"(r[2]), "=r"(r[3]) : "r"(addr));
}
__device__ __forceinline__ void ldmx4t(uint32_t* r, uint32_t addr) {
    asm volatile("ldmatrix.sync.aligned.m8n8.x4.trans.shared.b16 {%0,%1,%2,%3}, [%4];"
        : "=r"(r[0]), "=r"(r[1]), "=r"(r[2]), "=r"(r[3]) : "r"(addr));
}
__device__ __forceinline__ void mma16816(float* d, const uint32_t* a,
                                         const uint32_t* b) {
    asm volatile(
        "mma.sync.aligned.m16n8k16.row.col.f32.f16.f16.f32 "
        "{%0,%1,%2,%3}, {%4,%5,%6,%7}, {%8,%9}, {%0,%1,%2,%3};"
        : "+f"(d[0]), "+f"(d[1]), "+f"(d[2]), "+f"(d[3])
        : "r"(a[0]), "r"(a[1]), "r"(a[2]), "r"(a[3]), "r"(b[0]), "r"(b[1]));
}

// ---------------------------------------------------------------------------
// prep: convert all three weight matrices fp32 -> fp16 in ONE launch.
// ---------------------------------------------------------------------------
#define PW1 (VDIM_*DM_/4)
#define PW2 (PW1 + ADIM_*DM_/4)
#define PW3 (PW2 + XDIM_*HID_/4)
__global__ __launch_bounds__(256) void prep_all(
    const float* __restrict__ Wv, const float* __restrict__ Wa,
    const float* __restrict__ W1)
{
    int i = blockIdx.x * 256 + threadIdx.x;
    const float* src;
    __half* dst;
    int off;
    if (i < PW1)      { src = Wv; dst = g_wv; off = i; }
    else if (i < PW2) { src = Wa; dst = g_wa; off = i - PW1; }
    else if (i < PW3) { src = W1; dst = g_w1; off = i - PW2; }
    else return;
    float4 v = ((const float4*)src)[off];
    uint2 o = make_uint2(pkh2(v.x, v.y), pkh2(v.z, v.w));
    *(uint2*)(dst + (size_t)off * 4) = o;
}

// ---------------------------------------------------------------------------
// Fused projection GEMM + bias + LayerNorm epilogue.
// CTA tile 64 x 256 (full DM width -> complete rows per CTA), BK=32,
// 8 warps (2 row-blocks x 4 col-blocks), warp tile 32x64, 2-stage pipeline,
// LDG fp32 -> cvt fp16 -> STS for A, cp.async for B.
// Epilogue: stage C in smem (64 x 260 fp32), bias+LN per row (4 threads/row),
// write LN'd output once. MODE 0: g_v + g_rv. MODE 1: g_a.
// ---------------------------------------------------------------------------
#define PALD 40                       // A smem ld (halves)
#define PBLD 264                      // B smem ld (halves), 132-word rows
#define PAH  (64*PALD)                // 2560 halves
#define PSTG (PAH + 32*PBLD)          // 11008 halves = 22016 B per stage
#define PCLD 260                      // epilogue C ld (floats)

template<int NCH, int MODE>
__device__ __forceinline__ void proj_body(
    char* smraw, const float* __restrict__ A, const __half* __restrict__ Bt,
    const float* __restrict__ bias, float* __restrict__ Cout)
{
    __half* sh = (__half*)smraw;
    const int tid  = threadIdx.x;
    const int lane = tid & 31;
    const int warp = tid >> 5;
    const int wr   = warp >> 2;         // 0..1 (32-row block)
    const int wc   = warp & 3;          // 0..3 (64-col block)
    const int row0 = blockIdx.x * 64;
    const int KD   = NCH * 32;

    float acc[2][8][4];
#pragma unroll
    for (int u = 0; u < 2; u++)
#pragma unroll
        for (int w = 0; w < 8; w++)
#pragma unroll
            for (int x = 0; x < 4; x++) acc[u][w][x] = 0.f;

    const int lrow = lane & 15;
    const int lhal = lane >> 4;
    const uint32_t loA = (uint32_t)(((wr * 32 + lrow) * PALD + lhal * 8) * 2);
    const uint32_t loB = (uint32_t)((lrow * PBLD + wc * 64 + lhal * 8) * 2);

    // A copy mapping: 64 rows x 32 cols, 2 float4 per thread
    const int ar = tid >> 3;            // rows 0..31 (+32*j)
    const int ac = (tid & 7) << 2;      // cols 0,4..28

    float4 areg[2];
    auto ldgA = [&](int i) {
        const float* Ab = A + (size_t)row0 * KD + i * 32;
#pragma unroll
        for (int j = 0; j < 2; j++)
            areg[j] = *(const float4*)(Ab + (size_t)(ar + 32 * j) * KD + ac);
    };
    auto stsA = [&](__half* As) {
#pragma unroll
        for (int j = 0; j < 2; j++) {
            uint2 o = make_uint2(pkh2(areg[j].x, areg[j].y),
                                 pkh2(areg[j].z, areg[j].w));
            *(uint2*)(As + (ar + 32 * j) * PALD + ac) = o;
        }
    };
    auto cpB = [&](int i, __half* Bs) {
        // 32 rows x 32 segs of 8 halves = 1024 CP16s / 256 thr = 4 each
#pragma unroll
        for (int j = 0; j < 4; j++) {
            int idx = tid + j * 256;
            int r   = idx >> 5;
            int sg  = (idx & 31) << 3;
            CP16(smem_u32(Bs + r * PBLD + sg),
                 Bt + (size_t)(i * 32 + r) * DM_ + sg);
        }
    };

    // Prologue
    {
        ldgA(0); stsA(sh);
        cpB(0, sh + PAH);
        CP_COMMIT();
    }

#pragma unroll
    for (int i = 0; i < NCH; i++) {
        __half* As = sh + (i & 1) * PSTG;
        __half* Bs = As + PAH;
        if (i + 1 < NCH) {
            cpB(i + 1, sh + ((i + 1) & 1) * PSTG + PAH);
            CP_COMMIT();
            ldgA(i + 1);
            CP_WAIT(1);
        } else {
            CP_WAIT(0);
        }
        __syncthreads();
        if (i + 1 < NCH) stsA(sh + ((i + 1) & 1) * PSTG);  // into NEXT stage
        // NOTE: stsA writes stage (i+1)&1 which is not read until next iter;
        // the barrier above fenced its previous readers (chunk i-1).

        const uint32_t uA = smem_u32(As) + loA;
        const uint32_t uB = smem_u32(Bs) + loB;
#pragma unroll
        for (int kk = 0; kk < 32; kk += 16) {
            uint32_t af[2][4], bf[4][4];
#pragma unroll
            for (int u = 0; u < 2; u++)
                ldmx4(af[u], uA + (uint32_t)((u * 16 * PALD + kk) * 2));
#pragma unroll
            for (int v = 0; v < 4; v++)
                ldmx4t(bf[v], uB + (uint32_t)((kk * PBLD + v * 16) * 2));
#pragma unroll
            for (int u = 0; u < 2; u++)
#pragma unroll
                for (int v = 0; v < 4; v++) {
                    mma16816(acc[u][v * 2 + 0], af[u], bf[v] + 0);
                    mma16816(acc[u][v * 2 + 1], af[u], bf[v] + 2);
                }
        }
        __syncthreads();
    }

    // Epilogue: stage C (64 x 260 fp32), then bias + LN per row
    float* Cs = (float*)smraw;
    const int tg = lane >> 2;
    const int tt = lane & 3;
#pragma unroll
    for (int u = 0; u < 2; u++)
#pragma unroll
        for (int w = 0; w < 8; w++) {
            int mm = wr * 32 + u * 16 + tg;
            int nn = wc * 64 + w * 8 + tt * 2;
            *(float2*)(Cs + mm * PCLD + nn) =
                make_float2(acc[u][w][0], acc[u][w][1]);
            *(float2*)(Cs + (mm + 8) * PCLD + nn) =
                make_float2(acc[u][w][2], acc[u][w][3]);
        }
    __syncthreads();

    // 4 threads per row; thread sub covers cols sub*64 .. +63
    const int row = tid >> 2;
    const int sub = tid & 3;
    const int c0  = sub * 64;
    float s = 0.f, q = 0.f;
#pragma unroll
    for (int c4 = 0; c4 < 16; c4++) {
        float4 x = *(float4*)(Cs + row * PCLD + c0 + c4 * 4);
        float4 b = *(const float4*)(bias + c0 + c4 * 4);
        x.x += b.x; x.y += b.y; x.z += b.z; x.w += b.w;
        s += x.x + x.y + x.z + x.w;
        q = fmaf(x.x, x.x, fmaf(x.y, x.y, fmaf(x.z, x.z, fmaf(x.w, x.w, q))));
    }
    s += __shfl_xor_sync(0xffffffffu, s, 1);
    q += __shfl_xor_sync(0xffffffffu, q, 1);
    s += __shfl_xor_sync(0xffffffffu, s, 2);
    q += __shfl_xor_sync(0xffffffffu, q, 2);
    float mu   = s * (1.f / 256.f);
    float var  = fmaxf(q * (1.f / 256.f) - mu * mu, 0.f);
    float rstd = rsqrtf(var + 1e-5f);
    if (MODE == 0 && sub == 0) {
        float l2 = sqrtf(256.f * var) * rstd;
        g_rv[row0 + row] = 1.f / fmaxf(l2, 1e-8f);
    }
#pragma unroll
    for (int c4 = 0; c4 < 16; c4++) {
        float4 x = *(float4*)(Cs + row * PCLD + c0 + c4 * 4);
        float4 b = *(const float4*)(bias + c0 + c4 * 4);
        float4 o = {(x.x + b.x - mu) * rstd, (x.y + b.y - mu) * rstd,
                    (x.z + b.z - mu) * rstd, (x.w + b.w - mu) * rstd};
        *(float4*)(Cout + (size_t)(row0 + row) * DM_ + c0 + c4 * 4) = o;
    }
}

__global__ __launch_bounds__(256, 2) void gemm_proj(
    const float* __restrict__ video, const float* __restrict__ audio,
    const float* __restrict__ bv, const float* __restrict__ ba)
{
    extern __shared__ __align__(16) char smraw[];
    if (blockIdx.z == 0)
        proj_body<VDIM_/32, 0>(smraw, video, g_wv, bv, g_v);
    else
        proj_body<ADIM_/32, 1>(smraw, audio, g_wa, ba, g_a);
}

// ---------------------------------------------------------------------------
// mlp GEMM: CTA 128x128, BK=64, pure cp.async, fused gelu.W2 epilogue (R12).
// ---------------------------------------------------------------------------
#define BLDH 136
#define MALD 72                       // BK+8
#define MAH  (128*MALD)
#define MSTG (MAH + 64*BLDH)          // 17920 halves = 35840 B

__global__ __launch_bounds__(256, 2) void gemm_mlp(
    const float* __restrict__ b1v, const float* __restrict__ W2v)
{
    extern __shared__ __align__(16) char smraw[];
    constexpr int NCH = XDIM_ / 64;
    __half* sh = (__half*)smraw;
    const int tid  = threadIdx.x;
    const int lane = tid & 31;
    const int warp = tid >> 5;
    const int wr   = warp >> 1;
    const int wc   = warp & 1;
    const int row0 = blockIdx.x * 128;
    const int n0   = blockIdx.y * 128;

    float acc[2][8][4];
#pragma unroll
    for (int u = 0; u < 2; u++)
#pragma unroll
        for (int w = 0; w < 8; w++)
#pragma unroll
            for (int x = 0; x < 4; x++) acc[u][w][x] = 0.f;

    const int lrow = lane & 15;
    const int lhal = lane >> 4;
    const uint32_t loA = (uint32_t)(((wr * 32 + lrow) * MALD + lhal * 8) * 2);
    const uint32_t loB = (uint32_t)((lrow * BLDH + wc * 64 + lhal * 8) * 2);

    auto cpA = [&](int i, __half* As) {
        // 128 rows x 8 segs = 1024 CP16 / 256 = 4 each
#pragma unroll
        for (int j = 0; j < 4; j++) {
            int idx = tid + j * 256;
            int r   = idx >> 3;
            int sg  = (idx & 7) << 3;
            CP16(smem_u32(As + r * MALD + sg),
                 g_Xh + (size_t)(row0 + r) * XDIM_ + i * 64 + sg);
        }
    };
    auto cpB = [&](int i, __half* Bs) {
        // 64 rows x 16 segs = 1024 CP16 / 256 = 4 each
#pragma unroll
        for (int j = 0; j < 4; j++) {
            int idx = tid + j * 256;
            int r   = idx >> 4;
            int sg  = (idx & 15) << 3;
            CP16(smem_u32(Bs + r * BLDH + sg),
                 g_w1 + (size_t)(i * 64 + r) * HID_ + n0 + sg);
        }
    };

    { cpA(0, sh); cpB(0, sh + MAH); CP_COMMIT(); }

#pragma unroll
    for (int i = 0; i < NCH; i++) {
        __half* As = sh + (i & 1) * MSTG;
        __half* Bs = As + MAH;
        if (i + 1 < NCH) {
            __half* Asn = sh + ((i + 1) & 1) * MSTG;
            cpA(i + 1, Asn);
            cpB(i + 1, Asn + MAH);
            CP_COMMIT();
            CP_WAIT(1);
        } else {
            CP_WAIT(0);
        }
        __syncthreads();

        const uint32_t uA = smem_u32(As) + loA;
        const uint32_t uB = smem_u32(Bs) + loB;
#pragma unroll
        for (int kk = 0; kk < 64; kk += 16) {
            uint32_t af[2][4], bf[4][4];
#pragma unroll
            for (int u = 0; u < 2; u++)
                ldmx4(af[u], uA + (uint32_t)((u * 16 * MALD + kk) * 2));
#pragma unroll
            for (int v = 0; v < 4; v++)
                ldmx4t(bf[v], uB + (uint32_t)((kk * BLDH + v * 16) * 2));
#pragma unroll
            for (int u = 0; u < 2; u++)
#pragma unroll
                for (int v = 0; v < 4; v++) {
                    mma16816(acc[u][v * 2 + 0], af[u], bf[v] + 0);
                    mma16816(acc[u][v * 2 + 1], af[u], bf[v] + 2);
                }
        }
        __syncthreads();
    }

    const int tg = lane >> 2;
    const int tt = lane & 3;
    float* Cs = (float*)smraw;   // 128 x 132
#pragma unroll
    for (int u = 0; u < 2; u++)
#pragma unroll
        for (int w = 0; w < 8; w++) {
            int mm = wr * 32 + u * 16 + tg;
            int nn = wc * 64 + w * 8 + tt * 2;
            *(float2*)(Cs + mm * 132 + nn) =
                make_float2(acc[u][w][0], acc[u][w][1]);
            *(float2*)(Cs + (mm + 8) * 132 + nn) =
                make_float2(acc[u][w][2], acc[u][w][3]);
        }
    __syncthreads();

    float b1f[4], w2f[4];
#pragma unroll
    for (int q = 0; q < 4; q++) {
        int gcol = n0 + lane + q * 32;
        b1f[q] = b1v[gcol];
        w2f[q] = W2v[gcol];
    }
#pragma unroll
    for (int rr = 0; rr < 16; rr++) {
        int r = warp * 16 + rr;
        float p = 0.f;
#pragma unroll
        for (int q = 0; q < 4; q++) {
            float x = Cs[r * 132 + lane + q * 32] + b1f[q];
            float h = 0.5f * x * (1.f + erff(x * 0.7071067811865476f));
            p = fmaf(h, w2f[q], p);
        }
#pragma unroll
        for (int off = 16; off > 0; off >>= 1)
            p += __shfl_xor_sync(0xffffffffu, p, off);
        if (lane == 0)
            g_plog[(size_t)(row0 + r) * NBLK_ + blockIdx.y] = p;
    }
}

// ---------------------------------------------------------------------------
// ctx: temporal shift + causal window avg via 7-tap identity + l2 norms + X.
// acc = (1-a)*A[base] + sum(A[base+1..base+5]) + a*A[base+6], base = t-5-ni,
// valid when t >= ni+5; clamped slow path otherwise (t < 11 only).
// 4 rows/block, 64 threads/row, float4 per thread.
// ---------------------------------------------------------------------------
__global__ __launch_bounds__(256) void ctx_kernel(const float* __restrict__ theta)
{
    __shared__ float red2[4][2];
    const int tid = threadIdx.x;
    const int rl  = tid >> 6;
    const int q   = tid & 63;
    const int row = blockIdx.x * 4 + rl;
    const int b   = row >> 11;
    const int t   = row & 2047;

    float th    = fminf(fmaxf(theta[0], -12.f), 12.f);
    float delta = 2.f + 4.f / (1.f + expf(-th));
    float nf    = floorf(delta);
    float alpha = delta - nf;
    int   ni    = (int)nf;

    const float* ab = g_a + (size_t)b * T_ * DM_;
    float4 ac;
    if (t >= ni + 5) {
        const float* base = ab + (size_t)(t - 5 - ni) * DM_ + q * 4;
        float4 x0 = *(const float4*)(base);
        float4 x6 = *(const float4*)(base + 6 * DM_);
        float4 sm = {0.f, 0.f, 0.f, 0.f};
#pragma unroll
        for (int j = 1; j <= 5; j++) {
            float4 xj = *(const float4*)(base + j * DM_);
            sm.x += xj.x; sm.y += xj.y; sm.z += xj.z; sm.w += xj.w;
        }
        const float w0 = 1.f - alpha, c6 = 1.f / 6.f;
        ac.x = (w0 * x0.x + sm.x + alpha * x6.x) * c6;
        ac.y = (w0 * x0.y + sm.y + alpha * x6.y) * c6;
        ac.z = (w0 * x0.z + sm.z + alpha * x6.z) * c6;
        ac.w = (w0 * x0.w + sm.w + alpha * x6.w) * c6;
    } else {
        const int lo = max(0, t - 5);
        const float inv_cnt = 1.f / (float)(t - lo + 1);
        float4 acc = {0.f, 0.f, 0.f, 0.f};
        for (int tau = lo; tau <= t; tau++) {
            int i0 = min(max(tau - ni, 0), T_ - 1);
            int i1 = min(i0 + 1, T_ - 1);
            float4 x0 = *(const float4*)(ab + (size_t)i0 * DM_ + q * 4);
            float4 x1 = *(const float4*)(ab + (size_t)i1 * DM_ + q * 4);
            acc.x += (1.f - alpha) * x0.x + alpha * x1.x;
            acc.y += (1.f - alpha) * x0.y + alpha * x1.y;
            acc.z += (1.f - alpha) * x0.z + alpha * x1.z;
            acc.w += (1.f - alpha) * x0.w + alpha * x1.w;
        }
        ac = make_float4(acc.x * inv_cnt, acc.y * inv_cnt,
                         acc.z * inv_cnt, acc.w * inv_cnt);
    }

    float ss = ac.x * ac.x + ac.y * ac.y + ac.z * ac.z + ac.w * ac.w;
#pragma unroll
    for (int off = 16; off > 0; off >>= 1)
        ss += __shfl_xor_sync(0xffffffffu, ss, off);
    const int wp = tid >> 5;
    if ((tid & 31) == 0) red2[wp >> 1][wp & 1] = ss;
    __syncthreads();
    float tot = red2[rl][0] + red2[rl][1];
    float ra  = 1.f / fmaxf(sqrtf(tot), 1e-8f);

    float4 vv = *(const float4*)(g_v + (size_t)row * DM_ + q * 4);
    float rv  = g_rv[row];

    *(float4*)(g_actx + (size_t)row * DM_ + q * 4) = ac;

    float vnx = vv.x * rv, vny = vv.y * rv, vnz = vv.z * rv, vnw = vv.w * rv;
    float anx = ac.x * ra, any_ = ac.y * ra, anz = ac.z * ra, anw = ac.w * ra;

    __half* xr = g_Xh + (size_t)row * XDIM_;
    *(uint2*)(xr + q * 4) =
        make_uint2(pkh2(anx, any_), pkh2(anz, anw));
    *(uint2*)(xr + DM_ + q * 4) =
        make_uint2(pkh2(vnx, vny), pkh2(vnz, vnw));
    *(uint2*)(xr + 2 * DM_ + q * 4) =
        make_uint2(pkh2(anx * vnx, any_ * vny), pkh2(anz * vnz, anw * vnw));
}

// ---------------------------------------------------------------------------
// out: finish logit, gate, mix. float4 per thread.
// ---------------------------------------------------------------------------
__global__ __launch_bounds__(256) void out_kernel(
    const float* __restrict__ b2, float* __restrict__ out)
{
    const int idx = blockIdx.x * 256 + threadIdx.x;
    const int row = idx >> 6;
    const int c4  = (idx & 63) << 2;
    float s = b2[0];
#pragma unroll
    for (int k = 0; k < NBLK_; k++) s += g_plog[(size_t)row * NBLK_ + k];
    s = fminf(fmaxf(s, -12.f), 12.f);
    float g = 1.f / (1.f + expf(-s));
    g = fminf(fmaxf(g, 0.05f), 0.95f);
    float4 ac = *(const float4*)(g_actx + (size_t)row * DM_ + c4);
    float4 vv = *(const float4*)(g_v + (size_t)row * DM_ + c4);
    float4 o  = {g * ac.x + (1.f - g) * vv.x, g * ac.y + (1.f - g) * vv.y,
                 g * ac.z + (1.f - g) * vv.z, g * ac.w + (1.f - g) * vv.w};
    *(float4*)(out + (size_t)row * DM_ + c4) = o;
}

// ---------------------------------------------------------------------------
extern "C" void kernel_launch(void* const* d_in, const int* in_sizes, int n_in,
                              void* d_out, int out_size)
{
    const float* video = (const float*)d_in[0];
    const float* audio = (const float*)d_in[1];
    const float* Wv    = (const float*)d_in[2];
    const float* bv    = (const float*)d_in[3];
    const float* Wa    = (const float*)d_in[4];
    const float* ba    = (const float*)d_in[5];
    const float* theta = (const float*)d_in[6];
    const float* W1    = (const float*)d_in[7];
    const float* b1    = (const float*)d_in[8];
    const float* W2    = (const float*)d_in[9];
    const float* b2    = (const float*)d_in[10];
    float* out = (float*)d_out;

    // proj smem: max(2 stages = 44032 B, epilogue Cs 64*260*4 = 66560 B)
    const int psm = 64 * PCLD * 4;            // 66560
    const int msm = 2 * MSTG * 2;             // 71680 (>= 128*132*4 epilogue)
    cudaFuncSetAttribute(gemm_proj,
        cudaFuncAttributeMaxDynamicSharedMemorySize, psm);
    cudaFuncSetAttribute(gemm_mlp,
        cudaFuncAttributeMaxDynamicSharedMemorySize, msm);

    prep_all<<<(PW3 + 255)/256, 256>>>(Wv, Wa, W1);
    gemm_proj<<<dim3(R_/64, 1, 2), 256, psm>>>(video, audio, bv, ba);
    ctx_kernel<<<R_/4, 256>>>(theta);
    gemm_mlp<<<dim3(R_/128, NBLK_), 256, msm>>>(b1, W2);
    out_kernel<<<(R_*64)/256, 256>>>(b2, out);
}

// round 15
// speedup vs baseline: 1.2588x; 1.0311x over previous
#include <cuda_runtime.h>
#include <cuda_fp16.h>
#include <math.h>
#include <stdint.h>

// Problem constants
#define B_    8
#define T_    2048
#define R_    (B_*T_)     // 16384 rows
#define VDIM_ 1024
#define ADIM_ 768
#define DM_   256
#define HID_  1024
#define XDIM_ 768         // 3*DM
#define NBLK_ 8           // HID / 128 column blocks for gate GEMM

// Scratch (__device__ globals; allocation-free rule)
__device__ __align__(16) float g_v[R_*DM_];      // LN'd video proj
__device__ float g_rv[R_];                       // 1/max(||v_row||,eps)
__device__ __align__(16) float g_a[R_*DM_];      // LN'd audio proj
__device__ __align__(16) float g_actx[R_*DM_];   // audio context
__device__ __align__(16) __half g_Xh[R_*XDIM_];  // [an, vn, an*vn] fp16
__device__ float g_plog[R_*NBLK_];               // partial logits
// fp16 weights
__device__ __align__(16) __half g_wv[VDIM_*DM_];
__device__ __align__(16) __half g_wa[ADIM_*DM_];
__device__ __align__(16) __half g_w1[XDIM_*HID_];

__device__ __forceinline__ uint32_t smem_u32(const void* p) {
    uint32_t a;
    asm("{ .reg .u64 t; cvta.to.shared.u64 t, %1; cvt.u32.u64 %0, t; }"
        : "=r"(a) : "l"(p));
    return a;
}
#define CP16(dst_u32, src_ptr) \
    asm volatile("cp.async.cg.shared.global [%0], [%1], 16;" \
                 :: "r"(dst_u32), "l"(src_ptr) : "memory")
#define CP_COMMIT() asm volatile("cp.async.commit_group;" ::: "memory")
#define CP_WAIT(n)  asm volatile("cp.async.wait_group %0;" :: "n"(n) : "memory")

__device__ __forceinline__ uint32_t pkh2(float a, float b) {
    __half2 h = __floats2half2_rn(a, b);
    return *reinterpret_cast<uint32_t*>(&h);
}
__device__ __forceinline__ void ldmx4(uint32_t* r, uint32_t addr) {
    asm volatile("ldmatrix.sync.aligned.m8n8.x4.shared.b16 {%0,%1,%2,%3}, [%4];"
        : "=r"(r[0]), "=r"(r[1]), "=r"(r[2]), "=r"(r[3]) : "r"(addr));
}
__device__ __forceinline__ void ldmx4t(uint32_t* r, uint32_t addr) {
    asm volatile("ldmatrix.sync.aligned.m8n8.x4.trans.shared.b16 {%0,%1,%2,%3}, [%4];"
        : "=r"(r[0]), "=r"(r[1]), "=r"(r[2]), "=r"(r[3]) : "r"(addr));
}
__device__ __forceinline__ void mma16816(float* d, const uint32_t* a,
                                         const uint32_t* b) {
    asm volatile(
        "mma.sync.aligned.m16n8k16.row.col.f32.f16.f16.f32 "
        "{%0,%1,%2,%3}, {%4,%5,%6,%7}, {%8,%9}, {%0,%1,%2,%3};"
        : "+f"(d[0]), "+f"(d[1]), "+f"(d[2]), "+f"(d[3])
        : "r"(a[0]), "r"(a[1]), "r"(a[2]), "r"(a[3]), "r"(b[0]), "r"(b[1]));
}

// ---------------------------------------------------------------------------
// prep: convert all three weight matrices fp32 -> fp16 in ONE launch.
// ---------------------------------------------------------------------------
#define PW1 (VDIM_*DM_/4)
#define PW2 (PW1 + ADIM_*DM_/4)
#define PW3 (PW2 + XDIM_*HID_/4)
__global__ __launch_bounds__(256) void prep_all(
    const float* __restrict__ Wv, const float* __restrict__ Wa,
    const float* __restrict__ W1)
{
    int i = blockIdx.x * 256 + threadIdx.x;
    const float* src;
    __half* dst;
    int off;
    if (i < PW1)      { src = Wv; dst = g_wv; off = i; }
    else if (i < PW2) { src = Wa; dst = g_wa; off = i - PW1; }
    else if (i < PW3) { src = W1; dst = g_w1; off = i - PW2; }
    else return;
    float4 v = ((const float4*)src)[off];
    uint2 o = make_uint2(pkh2(v.x, v.y), pkh2(v.z, v.w));
    *(uint2*)(dst + (size_t)off * 4) = o;
}

// ---------------------------------------------------------------------------
// Fused projection GEMM + bias + LayerNorm epilogue.
// CTA tile 64 x 256 (full DM width), BK=64 (half the chunks of R13),
// 8 warps (2 row x 4 col), warp tile 32x64, 2-stage pipeline.
// A: LDG fp32 (4 float4/thread) -> cvt fp16 -> STS. B: cp.async.
// Epilogue: stage C in smem (64 x 260 fp32), bias+LN per row (4 thr/row).
// MODE 0: g_v + g_rv. MODE 1: g_a.
// ---------------------------------------------------------------------------
#define PALD 72                       // A smem ld (halves) = BK+8
#define PBLD 264                      // B smem ld (halves)
#define PAH  (64*PALD)                // 4608 halves
#define PSTG (PAH + 64*PBLD)          // 21504 halves = 43008 B per stage
#define PCLD 260                      // epilogue C ld (floats)

template<int NCH, int MODE>
__device__ __forceinline__ void proj_body(
    char* smraw, const float* __restrict__ A, const __half* __restrict__ Bt,
    const float* __restrict__ bias, float* __restrict__ Cout)
{
    __half* sh = (__half*)smraw;
    const int tid  = threadIdx.x;
    const int lane = tid & 31;
    const int warp = tid >> 5;
    const int wr   = warp >> 2;         // 0..1 (32-row block)
    const int wc   = warp & 3;          // 0..3 (64-col block)
    const int row0 = blockIdx.x * 64;
    const int KD   = NCH * 64;

    float acc[2][8][4];
#pragma unroll
    for (int u = 0; u < 2; u++)
#pragma unroll
        for (int w = 0; w < 8; w++)
#pragma unroll
            for (int x = 0; x < 4; x++) acc[u][w][x] = 0.f;

    const int lrow = lane & 15;
    const int lhal = lane >> 4;
    const uint32_t loA = (uint32_t)(((wr * 32 + lrow) * PALD + lhal * 8) * 2);
    const uint32_t loB = (uint32_t)((lrow * PBLD + wc * 64 + lhal * 8) * 2);

    // A copy mapping: one row per thread-quad; 64 rows x 64 cols
    const int ar = tid >> 2;            // rows 0..63
    const int ac0 = (tid & 3) << 4;     // col base 0,16,32,48

    float4 areg[4];
    auto ldgA = [&](int i) {
        const float* Ab = A + (size_t)(row0 + ar) * KD + i * 64 + ac0;
#pragma unroll
        for (int j = 0; j < 4; j++)
            areg[j] = *(const float4*)(Ab + j * 4);
    };
    auto stsA = [&](__half* As) {
#pragma unroll
        for (int j = 0; j < 2; j++) {
            uint4 o;
            o.x = pkh2(areg[2*j].x,   areg[2*j].y);
            o.y = pkh2(areg[2*j].z,   areg[2*j].w);
            o.z = pkh2(areg[2*j+1].x, areg[2*j+1].y);
            o.w = pkh2(areg[2*j+1].z, areg[2*j+1].w);
            *(uint4*)(As + ar * PALD + ac0 + j * 8) = o;
        }
    };
    auto cpB = [&](int i, __half* Bs) {
        // 64 rows x 32 segs of 8 halves = 2048 CP16 / 256 thr = 8 each
#pragma unroll
        for (int j = 0; j < 8; j++) {
            int idx = tid + j * 256;
            int r   = idx >> 5;
            int sg  = (idx & 31) << 3;
            CP16(smem_u32(Bs + r * PBLD + sg),
                 Bt + (size_t)(i * 64 + r) * DM_ + sg);
        }
    };

    // Prologue
    {
        ldgA(0); stsA(sh);
        cpB(0, sh + PAH);
        CP_COMMIT();
        ldgA(1);
    }

#pragma unroll
    for (int i = 0; i < NCH; i++) {
        __half* As = sh + (i & 1) * PSTG;
        __half* Bs = As + PAH;
        if (i + 1 < NCH) {
            cpB(i + 1, sh + ((i + 1) & 1) * PSTG + PAH);
            CP_COMMIT();
            CP_WAIT(1);
        } else {
            CP_WAIT(0);
        }
        __syncthreads();
        if (i + 1 < NCH) {
            stsA(sh + ((i + 1) & 1) * PSTG);   // regs hold chunk i+1
            if (i + 2 < NCH) ldgA(i + 2);      // hide under chunk i compute
        }

        const uint32_t uA = smem_u32(As) + loA;
        const uint32_t uB = smem_u32(Bs) + loB;
#pragma unroll
        for (int kk = 0; kk < 64; kk += 16) {
            uint32_t af[2][4], bf[4][4];
#pragma unroll
            for (int u = 0; u < 2; u++)
                ldmx4(af[u], uA + (uint32_t)((u * 16 * PALD + kk) * 2));
#pragma unroll
            for (int v = 0; v < 4; v++)
                ldmx4t(bf[v], uB + (uint32_t)((kk * PBLD + v * 16) * 2));
#pragma unroll
            for (int u = 0; u < 2; u++)
#pragma unroll
                for (int v = 0; v < 4; v++) {
                    mma16816(acc[u][v * 2 + 0], af[u], bf[v] + 0);
                    mma16816(acc[u][v * 2 + 1], af[u], bf[v] + 2);
                }
        }
        __syncthreads();
    }

    // Epilogue: stage C (64 x 260 fp32), then bias + LN per row
    float* Cs = (float*)smraw;
    const int tg = lane >> 2;
    const int tt = lane & 3;
#pragma unroll
    for (int u = 0; u < 2; u++)
#pragma unroll
        for (int w = 0; w < 8; w++) {
            int mm = wr * 32 + u * 16 + tg;
            int nn = wc * 64 + w * 8 + tt * 2;
            *(float2*)(Cs + mm * PCLD + nn) =
                make_float2(acc[u][w][0], acc[u][w][1]);
            *(float2*)(Cs + (mm + 8) * PCLD + nn) =
                make_float2(acc[u][w][2], acc[u][w][3]);
        }
    __syncthreads();

    // 4 threads per row; thread sub covers cols sub*64 .. +63
    const int row = tid >> 2;
    const int sub = tid & 3;
    const int c0  = sub * 64;
    float s = 0.f, q = 0.f;
#pragma unroll
    for (int c4 = 0; c4 < 16; c4++) {
        float4 x = *(float4*)(Cs + row * PCLD + c0 + c4 * 4);
        float4 b = *(const float4*)(bias + c0 + c4 * 4);
        x.x += b.x; x.y += b.y; x.z += b.z; x.w += b.w;
        s += x.x + x.y + x.z + x.w;
        q = fmaf(x.x, x.x, fmaf(x.y, x.y, fmaf(x.z, x.z, fmaf(x.w, x.w, q))));
    }
    s += __shfl_xor_sync(0xffffffffu, s, 1);
    q += __shfl_xor_sync(0xffffffffu, q, 1);
    s += __shfl_xor_sync(0xffffffffu, s, 2);
    q += __shfl_xor_sync(0xffffffffu, q, 2);
    float mu   = s * (1.f / 256.f);
    float var  = fmaxf(q * (1.f / 256.f) - mu * mu, 0.f);
    float rstd = rsqrtf(var + 1e-5f);
    if (MODE == 0 && sub == 0) {
        float l2 = sqrtf(256.f * var) * rstd;
        g_rv[row0 + row] = 1.f / fmaxf(l2, 1e-8f);
    }
#pragma unroll
    for (int c4 = 0; c4 < 16; c4++) {
        float4 x = *(float4*)(Cs + row * PCLD + c0 + c4 * 4);
        float4 b = *(const float4*)(bias + c0 + c4 * 4);
        float4 o = {(x.x + b.x - mu) * rstd, (x.y + b.y - mu) * rstd,
                    (x.z + b.z - mu) * rstd, (x.w + b.w - mu) * rstd};
        *(float4*)(Cout + (size_t)(row0 + row) * DM_ + c0 + c4 * 4) = o;
    }
}

__global__ __launch_bounds__(256, 2) void gemm_proj(
    const float* __restrict__ video, const float* __restrict__ audio,
    const float* __restrict__ bv, const float* __restrict__ ba)
{
    extern __shared__ __align__(16) char smraw[];
    if (blockIdx.z == 0)
        proj_body<VDIM_/64, 0>(smraw, video, g_wv, bv, g_v);
    else
        proj_body<ADIM_/64, 1>(smraw, audio, g_wa, ba, g_a);
}

// ---------------------------------------------------------------------------
// mlp GEMM: CTA 128x128, BK=64, pure cp.async, fused gelu.W2 epilogue.
// ---------------------------------------------------------------------------
#define BLDH 136
#define MALD 72
#define MAH  (128*MALD)
#define MSTG (MAH + 64*BLDH)          // 17920 halves = 35840 B

__global__ __launch_bounds__(256, 2) void gemm_mlp(
    const float* __restrict__ b1v, const float* __restrict__ W2v)
{
    extern __shared__ __align__(16) char smraw[];
    constexpr int NCH = XDIM_ / 64;
    __half* sh = (__half*)smraw;
    const int tid  = threadIdx.x;
    const int lane = tid & 31;
    const int warp = tid >> 5;
    const int wr   = warp >> 1;
    const int wc   = warp & 1;
    const int row0 = blockIdx.x * 128;
    const int n0   = blockIdx.y * 128;

    float acc[2][8][4];
#pragma unroll
    for (int u = 0; u < 2; u++)
#pragma unroll
        for (int w = 0; w < 8; w++)
#pragma unroll
            for (int x = 0; x < 4; x++) acc[u][w][x] = 0.f;

    const int lrow = lane & 15;
    const int lhal = lane >> 4;
    const uint32_t loA = (uint32_t)(((wr * 32 + lrow) * MALD + lhal * 8) * 2);
    const uint32_t loB = (uint32_t)((lrow * BLDH + wc * 64 + lhal * 8) * 2);

    auto cpA = [&](int i, __half* As) {
#pragma unroll
        for (int j = 0; j < 4; j++) {
            int idx = tid + j * 256;
            int r   = idx >> 3;
            int sg  = (idx & 7) << 3;
            CP16(smem_u32(As + r * MALD + sg),
                 g_Xh + (size_t)(row0 + r) * XDIM_ + i * 64 + sg);
        }
    };
    auto cpB = [&](int i, __half* Bs) {
#pragma unroll
        for (int j = 0; j < 4; j++) {
            int idx = tid + j * 256;
            int r   = idx >> 4;
            int sg  = (idx & 15) << 3;
            CP16(smem_u32(Bs + r * BLDH + sg),
                 g_w1 + (size_t)(i * 64 + r) * HID_ + n0 + sg);
        }
    };

    { cpA(0, sh); cpB(0, sh + MAH); CP_COMMIT(); }

#pragma unroll
    for (int i = 0; i < NCH; i++) {
        __half* As = sh + (i & 1) * MSTG;
        __half* Bs = As + MAH;
        if (i + 1 < NCH) {
            __half* Asn = sh + ((i + 1) & 1) * MSTG;
            cpA(i + 1, Asn);
            cpB(i + 1, Asn + MAH);
            CP_COMMIT();
            CP_WAIT(1);
        } else {
            CP_WAIT(0);
        }
        __syncthreads();

        const uint32_t uA = smem_u32(As) + loA;
        const uint32_t uB = smem_u32(Bs) + loB;
#pragma unroll
        for (int kk = 0; kk < 64; kk += 16) {
            uint32_t af[2][4], bf[4][4];
#pragma unroll
            for (int u = 0; u < 2; u++)
                ldmx4(af[u], uA + (uint32_t)((u * 16 * MALD + kk) * 2));
#pragma unroll
            for (int v = 0; v < 4; v++)
                ldmx4t(bf[v], uB + (uint32_t)((kk * BLDH + v * 16) * 2));
#pragma unroll
            for (int u = 0; u < 2; u++)
#pragma unroll
                for (int v = 0; v < 4; v++) {
                    mma16816(acc[u][v * 2 + 0], af[u], bf[v] + 0);
                    mma16816(acc[u][v * 2 + 1], af[u], bf[v] + 2);
                }
        }
        __syncthreads();
    }

    const int tg = lane >> 2;
    const int tt = lane & 3;
    float* Cs = (float*)smraw;   // 128 x 132
#pragma unroll
    for (int u = 0; u < 2; u++)
#pragma unroll
        for (int w = 0; w < 8; w++) {
            int mm = wr * 32 + u * 16 + tg;
            int nn = wc * 64 + w * 8 + tt * 2;
            *(float2*)(Cs + mm * 132 + nn) =
                make_float2(acc[u][w][0], acc[u][w][1]);
            *(float2*)(Cs + (mm + 8) * 132 + nn) =
                make_float2(acc[u][w][2], acc[u][w][3]);
        }
    __syncthreads();

    float b1f[4], w2f[4];
#pragma unroll
    for (int q = 0; q < 4; q++) {
        int gcol = n0 + lane + q * 32;
        b1f[q] = b1v[gcol];
        w2f[q] = W2v[gcol];
    }
#pragma unroll
    for (int rr = 0; rr < 16; rr++) {
        int r = warp * 16 + rr;
        float p = 0.f;
#pragma unroll
        for (int q = 0; q < 4; q++) {
            float x = Cs[r * 132 + lane + q * 32] + b1f[q];
            float h = 0.5f * x * (1.f + erff(x * 0.7071067811865476f));
            p = fmaf(h, w2f[q], p);
        }
#pragma unroll
        for (int off = 16; off > 0; off >>= 1)
            p += __shfl_xor_sync(0xffffffffu, p, off);
        if (lane == 0)
            g_plog[(size_t)(row0 + r) * NBLK_ + blockIdx.y] = p;
    }
}

// ---------------------------------------------------------------------------
// ctx: temporal shift + causal window avg via 7-tap identity + l2 norms + X.
// ---------------------------------------------------------------------------
__global__ __launch_bounds__(256) void ctx_kernel(const float* __restrict__ theta)
{
    __shared__ float red2[4][2];
    const int tid = threadIdx.x;
    const int rl  = tid >> 6;
    const int q   = tid & 63;
    const int row = blockIdx.x * 4 + rl;
    const int b   = row >> 11;
    const int t   = row & 2047;

    float th    = fminf(fmaxf(theta[0], -12.f), 12.f);
    float delta = 2.f + 4.f / (1.f + expf(-th));
    float nf    = floorf(delta);
    float alpha = delta - nf;
    int   ni    = (int)nf;

    const float* ab = g_a + (size_t)b * T_ * DM_;
    float4 ac;
    if (t >= ni + 5) {
        const float* base = ab + (size_t)(t - 5 - ni) * DM_ + q * 4;
        float4 x0 = *(const float4*)(base);
        float4 x6 = *(const float4*)(base + 6 * DM_);
        float4 sm = {0.f, 0.f, 0.f, 0.f};
#pragma unroll
        for (int j = 1; j <= 5; j++) {
            float4 xj = *(const float4*)(base + j * DM_);
            sm.x += xj.x; sm.y += xj.y; sm.z += xj.z; sm.w += xj.w;
        }
        const float w0 = 1.f - alpha, c6 = 1.f / 6.f;
        ac.x = (w0 * x0.x + sm.x + alpha * x6.x) * c6;
        ac.y = (w0 * x0.y + sm.y + alpha * x6.y) * c6;
        ac.z = (w0 * x0.z + sm.z + alpha * x6.z) * c6;
        ac.w = (w0 * x0.w + sm.w + alpha * x6.w) * c6;
    } else {
        const int lo = max(0, t - 5);
        const float inv_cnt = 1.f / (float)(t - lo + 1);
        float4 acc = {0.f, 0.f, 0.f, 0.f};
        for (int tau = lo; tau <= t; tau++) {
            int i0 = min(max(tau - ni, 0), T_ - 1);
            int i1 = min(i0 + 1, T_ - 1);
            float4 x0 = *(const float4*)(ab + (size_t)i0 * DM_ + q * 4);
            float4 x1 = *(const float4*)(ab + (size_t)i1 * DM_ + q * 4);
            acc.x += (1.f - alpha) * x0.x + alpha * x1.x;
            acc.y += (1.f - alpha) * x0.y + alpha * x1.y;
            acc.z += (1.f - alpha) * x0.z + alpha * x1.z;
            acc.w += (1.f - alpha) * x0.w + alpha * x1.w;
        }
        ac = make_float4(acc.x * inv_cnt, acc.y * inv_cnt,
                         acc.z * inv_cnt, acc.w * inv_cnt);
    }

    float ss = ac.x * ac.x + ac.y * ac.y + ac.z * ac.z + ac.w * ac.w;
#pragma unroll
    for (int off = 16; off > 0; off >>= 1)
        ss += __shfl_xor_sync(0xffffffffu, ss, off);
    const int wp = tid >> 5;
    if ((tid & 31) == 0) red2[wp >> 1][wp & 1] = ss;
    __syncthreads();
    float tot = red2[rl][0] + red2[rl][1];
    float ra  = 1.f / fmaxf(sqrtf(tot), 1e-8f);

    float4 vv = *(const float4*)(g_v + (size_t)row * DM_ + q * 4);
    float rv  = g_rv[row];

    *(float4*)(g_actx + (size_t)row * DM_ + q * 4) = ac;

    float vnx = vv.x * rv, vny = vv.y * rv, vnz = vv.z * rv, vnw = vv.w * rv;
    float anx = ac.x * ra, any_ = ac.y * ra, anz = ac.z * ra, anw = ac.w * ra;

    __half* xr = g_Xh + (size_t)row * XDIM_;
    *(uint2*)(xr + q * 4) =
        make_uint2(pkh2(anx, any_), pkh2(anz, anw));
    *(uint2*)(xr + DM_ + q * 4) =
        make_uint2(pkh2(vnx, vny), pkh2(vnz, vnw));
    *(uint2*)(xr + 2 * DM_ + q * 4) =
        make_uint2(pkh2(anx * vnx, any_ * vny), pkh2(anz * vnz, anw * vnw));
}

// ---------------------------------------------------------------------------
// out: finish logit, gate, mix. float4 per thread.
// ---------------------------------------------------------------------------
__global__ __launch_bounds__(256) void out_kernel(
    const float* __restrict__ b2, float* __restrict__ out)
{
    const int idx = blockIdx.x * 256 + threadIdx.x;
    const int row = idx >> 6;
    const int c4  = (idx & 63) << 2;
    float s = b2[0];
#pragma unroll
    for (int k = 0; k < NBLK_; k++) s += g_plog[(size_t)row * NBLK_ + k];
    s = fminf(fmaxf(s, -12.f), 12.f);
    float g = 1.f / (1.f + expf(-s));
    g = fminf(fmaxf(g, 0.05f), 0.95f);
    float4 ac = *(const float4*)(g_actx + (size_t)row * DM_ + c4);
    float4 vv = *(const float4*)(g_v + (size_t)row * DM_ + c4);
    float4 o  = {g * ac.x + (1.f - g) * vv.x, g * ac.y + (1.f - g) * vv.y,
                 g * ac.z + (1.f - g) * vv.z, g * ac.w + (1.f - g) * vv.w};
    *(float4*)(out + (size_t)row * DM_ + c4) = o;
}

// ---------------------------------------------------------------------------
extern "C" void kernel_launch(void* const* d_in, const int* in_sizes, int n_in,
                              void* d_out, int out_size)
{
    const float* video = (const float*)d_in[0];
    const float* audio = (const float*)d_in[1];
    const float* Wv    = (const float*)d_in[2];
    const float* bv    = (const float*)d_in[3];
    const float* Wa    = (const float*)d_in[4];
    const float* ba    = (const float*)d_in[5];
    const float* theta = (const float*)d_in[6];
    const float* W1    = (const float*)d_in[7];
    const float* b1    = (const float*)d_in[8];
    const float* W2    = (const float*)d_in[9];
    const float* b2    = (const float*)d_in[10];
    float* out = (float*)d_out;

    // proj smem: max(2 stages = 86016 B, epilogue Cs = 66560 B) = 86016
    const int psm = 2 * PSTG * 2;             // 86016
    const int msm = 2 * MSTG * 2;             // 71680 (>= 128*132*4 epilogue)
    cudaFuncSetAttribute(gemm_proj,
        cudaFuncAttributeMaxDynamicSharedMemorySize, psm);
    cudaFuncSetAttribute(gemm_mlp,
        cudaFuncAttributeMaxDynamicSharedMemorySize, msm);

    prep_all<<<(PW3 + 255)/256, 256>>>(Wv, Wa, W1);
    gemm_proj<<<dim3(R_/64, 1, 2), 256, psm>>>(video, audio, bv, ba);
    ctx_kernel<<<R_/4, 256>>>(theta);
    gemm_mlp<<<dim3(R_/128, NBLK_), 256, msm>>>(b1, W2);
    out_kernel<<<(R_*64)/256, 256>>>(b2, out);
}